// round 2
// baseline (speedup 1.0000x reference)
#include <cuda_runtime.h>
#include <math.h>

#define SZ     4096
#define SEN    128
#define DWE    100
#define DC     128
#define CVAR   110          // word(100) + pos1(5) + pos2(5)
#define CCONST 160          // event(32) + 8*role(16)
#define J_TOT  330          // 3 taps * 110 channels
#define JB     30           // j-chunk staged in SMEM (330 = 11 * 30)
#define OUTD   984
#define GS     8            // samples per CTA in const_kernel
#define VSTRIDE 132         // padded row stride for v tile (cols 0..129 used)

// --- device-global scratch (no allocations allowed in kernel_launch) ---
__device__ __align__(16) float gWr[J_TOT * DC];        // W'[j][o], j = k*110 + c
__device__ __align__(16) float gW2[3 * CCONST * DC];   // W2[k][c2][o] for const channels
__device__ __align__(16) float gBase[SZ * 3 * DC];     // per-sample per-tap const contribution

// ============================================================================
// P0: reorganize conv_w (layout [o][c][k], strides 810/3/1) into GEMM layouts.
// ============================================================================
__global__ void prep_kernel(const float* __restrict__ conv_w) {
    int idx = blockIdx.x * blockDim.x + threadIdx.x;
    if (idx < J_TOT * DC) {
        int j = idx / DC, o = idx % DC;
        int k = j / CVAR, c = j % CVAR;
        gWr[idx] = conv_w[o * 810 + c * 3 + k];
    } else {
        int i2 = idx - J_TOT * DC;
        if (i2 < 3 * CCONST * DC) {
            int kc = i2 / DC, o = i2 % DC;
            int k = kc / CCONST, c2 = kc % CCONST;
            gW2[i2] = conv_w[o * 810 + (CVAR + c2) * 3 + k];
        }
    }
}

// ============================================================================
// P1: per-sample constant-channel conv contribution (base) + full loc branch.
// One CTA handles GS=8 samples (reuses each W2 element 8x in registers).
// ============================================================================
__global__ __launch_bounds__(256) void const_kernel(
    const int* __restrict__ loc, const int* __restrict__ loc_mark,
    const int* __restrict__ subtype, const int* __restrict__ argRole,
    const float* __restrict__ word_emb, const float* __restrict__ event_emb,
    const float* __restrict__ role_emb, float* __restrict__ out)
{
    __shared__ float evrl[GS][CCONST];
    int tid = threadIdx.x;
    int b0 = blockIdx.x * GS;

    // gather event/role embeddings for 8 samples
    for (int i = tid; i < GS * CCONST; i += 256) {
        int g = i / CCONST, c2 = i % CCONST;
        int b = b0 + g;
        float v;
        if (c2 < 32) v = event_emb[subtype[b] * 32 + c2];
        else {
            int r = (c2 - 32) >> 4, q = (c2 - 32) & 15;
            v = role_emb[argRole[b * 8 + r] * 16 + q];
        }
        evrl[g][c2] = v;
    }
    __syncthreads();

    // base[b][k][o] = evrl[b,:] dot W2[k][:,o]
    for (int t = tid; t < 3 * DC; t += 256) {
        int o = t % DC, k = t / DC;
        float s[GS];
        #pragma unroll
        for (int g = 0; g < GS; g++) s[g] = 0.f;
        const float* w2 = &gW2[k * CCONST * DC + o];
        for (int c2 = 0; c2 < CCONST; c2++) {
            float w = w2[c2 * DC];
            #pragma unroll
            for (int g = 0; g < GS; g++) s[g] = fmaf(evrl[g][c2], w, s[g]);
        }
        #pragma unroll
        for (int g = 0; g < GS; g++) gBase[(size_t)(b0 + g) * (3 * DC) + t] = s[g];
    }

    // loc branch: one warp per sample (mark is warp-uniform -> no divergence)
    int g = tid >> 5, lane = tid & 31;
    int b = b0 + g;
    const int* lb = &loc[b * 16];
    int mark = loc_mark[b];
    float* ob = &out[(size_t)b * OUTD + 384];
    for (int d = lane; d < DWE; d += 32) {
        #pragma unroll
        for (int i = 0; i < 4; i++)
            ob[i * DWE + d] = tanhf(word_emb[lb[i] * DWE + d]);
        float s = 0.f;
        for (int i = 0; i < mark; i++) s += word_emb[lb[4 + i] * DWE + d];
        ob[400 + d] = tanhf(s / (float)mark);
        ob[500 + d] = tanhf(word_emb[lb[4 + mark] * DWE + d]);
    }
}

// ============================================================================
// Main: one CTA per sample. SMEM v-tile + staged W tiles, 330-step rank-1 GEMM
// with 4s x 16o register tile per thread, fused masked-max + tanh epilogue.
// ============================================================================
__global__ __launch_bounds__(256) void main_kernel(
    const int* __restrict__ inp, const int* __restrict__ pos1, const int* __restrict__ pos2,
    const float* __restrict__ maskL, const float* __restrict__ maskM, const float* __restrict__ maskR,
    const float* __restrict__ word_emb, const float* __restrict__ pos_emb,
    const float* __restrict__ conv_b, float* __restrict__ out)
{
    extern __shared__ float sm[];
    float* sWt   = sm;                        // JB*128  = 3840 (16B aligned, first)
    float* sv    = sWt + JB * DC;             // 110*132 = 14520
    float* sMask = sv + CVAR * VSTRIDE;       // 3*128
    float* sBase = sMask + 3 * SEN;           // 3*128
    float* sCb   = sBase + 3 * DC;            // 128

    const int tid = threadIdx.x;
    const int b = blockIdx.x;
    const int lane = tid & 31, warp = tid >> 5;
    const int obase = warp * 16;

    // zero the v tile (covers the two padding columns 0 and 129)
    for (int i = tid; i < CVAR * VSTRIDE; i += 256) sv[i] = 0.f;

    // stage masks / base / bias
    for (int i = tid; i < 3 * SEN; i += 256) {
        float m = (i < 128) ? maskL[b * SEN + i]
                : (i < 256) ? maskM[b * SEN + i - 128]
                            : maskR[b * SEN + i - 256];
        sMask[i] = m;
        sBase[i] = gBase[(size_t)b * (3 * DC) + i];
    }
    if (tid < DC) sCb[tid] = conv_b[tid];
    __syncthreads();

    // gather word embeddings: v[c][s+1], rows are channels, cols are positions
    const int* inpb = inp + b * SEN;
    for (int idx = tid; idx < SEN * 25; idx += 256) {
        int s = idx / 25, q = idx % 25;
        const float4 w4 = ((const float4*)word_emb)[inpb[s] * 25 + q];
        int c = q * 4;
        sv[(c + 0) * VSTRIDE + s + 1] = w4.x;
        sv[(c + 1) * VSTRIDE + s + 1] = w4.y;
        sv[(c + 2) * VSTRIDE + s + 1] = w4.z;
        sv[(c + 3) * VSTRIDE + s + 1] = w4.w;
    }
    // position embeddings: channels 100..109
    const int* p1b = pos1 + b * SEN;
    const int* p2b = pos2 + b * SEN;
    for (int idx = tid; idx < SEN * 10; idx += 256) {
        int s = idx / 10, q = idx % 10;
        int p = (q < 5) ? p1b[s] : p2b[s];
        int d = (q < 5) ? q : q - 5;
        sv[(100 + q) * VSTRIDE + s + 1] = pos_emb[p * 5 + d];
    }

    // ---- main GEMM: C[s,o] += A[s,j] * W'[j,o], A[s, k*110+c] = v[c][s+k] ----
    float acc[4][16];
    #pragma unroll
    for (int i = 0; i < 4; i++)
        #pragma unroll
        for (int t = 0; t < 16; t++) acc[i][t] = 0.f;

    for (int chunk = 0; chunk < J_TOT; chunk += JB) {
        __syncthreads();   // previous tile consumed (and, on iter 0, v fills done)
        {
            const float4* src = (const float4*)&gWr[chunk * DC];
            float4* dst = (float4*)sWt;
            for (int i = tid; i < JB * DC / 4; i += 256) dst[i] = src[i];
        }
        __syncthreads();
        #pragma unroll 6
        for (int jj = 0; jj < JB; jj++) {
            int j = chunk + jj;
            int k = (j >= 220) ? 2 : (j >= 110) ? 1 : 0;
            int c = j - k * CVAR;
            const float* vr = &sv[c * VSTRIDE + k + lane];
            float a0 = vr[0], a1 = vr[32], a2 = vr[64], a3 = vr[96];
            const float4* wp = (const float4*)&sWt[jj * DC + obase];
            float4 w0 = wp[0], w1 = wp[1], w2 = wp[2], w3 = wp[3];
            float w[16] = {w0.x, w0.y, w0.z, w0.w, w1.x, w1.y, w1.z, w1.w,
                           w2.x, w2.y, w2.z, w2.w, w3.x, w3.y, w3.z, w3.w};
            #pragma unroll
            for (int t = 0; t < 16; t++) {
                acc[0][t] = fmaf(a0, w[t], acc[0][t]);
                acc[1][t] = fmaf(a1, w[t], acc[1][t]);
                acc[2][t] = fmaf(a2, w[t], acc[2][t]);
                acc[3][t] = fmaf(a3, w[t], acc[3][t]);
            }
        }
    }

    // ---- epilogue: bias + edge-corrected base, masked max over s, tanh ----
    float mvL[4], mvM[4], mvR[4];
    #pragma unroll
    for (int i = 0; i < 4; i++) {
        int s = lane + 32 * i;
        mvL[i] = sMask[s];
        mvM[i] = sMask[128 + s];
        mvR[i] = sMask[256 + s];
    }
    float* outb = out + (size_t)b * OUTD;
    #pragma unroll
    for (int t = 0; t < 16; t++) {
        int o = obase + t;
        float cb  = sCb[o];
        float bs0 = sBase[o], bs1 = sBase[128 + o], bs2 = sBase[256 + o];
        float pL = -1e30f, pM = -1e30f, pR = -1e30f;
        #pragma unroll
        for (int i = 0; i < 4; i++) {
            int s = lane + 32 * i;
            float cv = acc[i][t] + cb + bs1;
            if (s > 0)   cv += bs0;   // k=0 tap valid only when s-1 >= 0
            if (s < 127) cv += bs2;   // k=2 tap valid only when s+1 <= 127
            pL = fmaxf(pL, cv * mvL[i]);
            pM = fmaxf(pM, cv * mvM[i]);
            pR = fmaxf(pR, cv * mvR[i]);
        }
        #pragma unroll
        for (int off = 16; off > 0; off >>= 1) {
            pL = fmaxf(pL, __shfl_xor_sync(0xffffffffu, pL, off));
            pM = fmaxf(pM, __shfl_xor_sync(0xffffffffu, pM, off));
            pR = fmaxf(pR, __shfl_xor_sync(0xffffffffu, pR, off));
        }
        if (lane == 0) {
            outb[o]       = tanhf(pL);
            outb[128 + o] = tanhf(pM);
            outb[256 + o] = tanhf(pR);
        }
    }
}

// ============================================================================
extern "C" void kernel_launch(void* const* d_in, const int* in_sizes, int n_in,
                              void* d_out, int out_size) {
    const int*   inp       = (const int*)d_in[0];
    const int*   pos1      = (const int*)d_in[1];
    const int*   pos2      = (const int*)d_in[2];
    const int*   loc       = (const int*)d_in[3];
    const int*   loc_mark  = (const int*)d_in[4];
    const int*   subtype   = (const int*)d_in[5];
    const int*   argRole   = (const int*)d_in[6];
    const float* maskL     = (const float*)d_in[7];
    const float* maskM     = (const float*)d_in[8];
    const float* maskR     = (const float*)d_in[9];
    const float* word_emb  = (const float*)d_in[10];
    const float* pos_emb   = (const float*)d_in[11];
    const float* event_emb = (const float*)d_in[12];
    const float* role_emb  = (const float*)d_in[13];
    const float* conv_w    = (const float*)d_in[14];
    const float* conv_b    = (const float*)d_in[15];
    float* out = (float*)d_out;

    int prep_elems = J_TOT * DC + 3 * CCONST * DC;
    prep_kernel<<<(prep_elems + 255) / 256, 256>>>(conv_w);
    const_kernel<<<SZ / GS, 256>>>(loc, loc_mark, subtype, argRole,
                                   word_emb, event_emb, role_emb, out);
    size_t smem = (size_t)(JB * DC + CVAR * VSTRIDE + 3 * SEN + 3 * DC + DC) * sizeof(float);
    cudaFuncSetAttribute(main_kernel, cudaFuncAttributeMaxDynamicSharedMemorySize, (int)smem);
    main_kernel<<<SZ, 256, smem>>>(inp, pos1, pos2, maskL, maskM, maskR,
                                   word_emb, pos_emb, conv_b, out);
}

// round 3
// speedup vs baseline: 1.1556x; 1.1556x over previous
#include <cuda_runtime.h>
#include <math.h>

#define SZ     4096
#define SEN    128
#define DWE    100
#define DC     128
#define CVAR   110          // word(100) + pos1(5) + pos2(5)
#define CCONST 160          // event(32) + 8*role(16)
#define J_TOT  330          // 3 taps * 110 channels
#define JB     30           // j-chunk staged in SMEM (330 = 11 * 30)
#define OUTD   984
#define GS     8            // samples per CTA in const_kernel
#define VSTRIDE 132         // padded row stride for v tile (cols 0..129 used)

typedef unsigned long long u64;

// --- device-global scratch (no allocations allowed in kernel_launch) ---
__device__ __align__(16) float gWr[J_TOT * DC];        // W'[j][o], j = k*110 + c
__device__ __align__(16) float gW2[3 * CCONST * DC];   // W2[k][c2][o] for const channels
__device__ __align__(16) float gBase[SZ * 3 * DC];     // per-sample per-tap const contribution

// ============================================================================
// P0: reorganize conv_w (layout [o][c][k], strides 810/3/1) into GEMM layouts.
// ============================================================================
__global__ void prep_kernel(const float* __restrict__ conv_w) {
    int idx = blockIdx.x * blockDim.x + threadIdx.x;
    if (idx < J_TOT * DC) {
        int j = idx / DC, o = idx % DC;
        int k = j / CVAR, c = j % CVAR;
        gWr[idx] = conv_w[o * 810 + c * 3 + k];
    } else {
        int i2 = idx - J_TOT * DC;
        if (i2 < 3 * CCONST * DC) {
            int kc = i2 / DC, o = i2 % DC;
            int k = kc / CCONST, c2 = kc % CCONST;
            gW2[i2] = conv_w[o * 810 + (CVAR + c2) * 3 + k];
        }
    }
}

// ============================================================================
// P1: per-sample constant-channel conv contribution (base) + full loc branch.
// ============================================================================
__global__ __launch_bounds__(256) void const_kernel(
    const int* __restrict__ loc, const int* __restrict__ loc_mark,
    const int* __restrict__ subtype, const int* __restrict__ argRole,
    const float* __restrict__ word_emb, const float* __restrict__ event_emb,
    const float* __restrict__ role_emb, float* __restrict__ out)
{
    __shared__ float evrl[GS][CCONST];
    int tid = threadIdx.x;
    int b0 = blockIdx.x * GS;

    for (int i = tid; i < GS * CCONST; i += 256) {
        int g = i / CCONST, c2 = i % CCONST;
        int b = b0 + g;
        float v;
        if (c2 < 32) v = event_emb[subtype[b] * 32 + c2];
        else {
            int r = (c2 - 32) >> 4, q = (c2 - 32) & 15;
            v = role_emb[argRole[b * 8 + r] * 16 + q];
        }
        evrl[g][c2] = v;
    }
    __syncthreads();

    for (int t = tid; t < 3 * DC; t += 256) {
        int o = t % DC, k = t / DC;
        float s[GS];
        #pragma unroll
        for (int g = 0; g < GS; g++) s[g] = 0.f;
        const float* w2 = &gW2[k * CCONST * DC + o];
        for (int c2 = 0; c2 < CCONST; c2++) {
            float w = w2[c2 * DC];
            #pragma unroll
            for (int g = 0; g < GS; g++) s[g] = fmaf(evrl[g][c2], w, s[g]);
        }
        #pragma unroll
        for (int g = 0; g < GS; g++) gBase[(size_t)(b0 + g) * (3 * DC) + t] = s[g];
    }

    // loc branch: one warp per sample
    int g = tid >> 5, lane = tid & 31;
    int b = b0 + g;
    const int* lb = &loc[b * 16];
    int mark = loc_mark[b];
    float* ob = &out[(size_t)b * OUTD + 384];
    for (int d = lane; d < DWE; d += 32) {
        #pragma unroll
        for (int i = 0; i < 4; i++)
            ob[i * DWE + d] = tanhf(word_emb[lb[i] * DWE + d]);
        float s = 0.f;
        for (int i = 0; i < mark; i++) s += word_emb[lb[4 + i] * DWE + d];
        ob[400 + d] = tanhf(s / (float)mark);
        ob[500 + d] = tanhf(word_emb[lb[4 + mark] * DWE + d]);
    }
}

// ============================================================================
// Main: one CTA per sample. SMEM v-tile + staged W tiles, 330-step rank-1 GEMM.
// Inner product uses packed fma.rn.f32x2: accumulators pair adjacent output
// channels (t=2p, 2p+1) so W pairs load pre-packed from SMEM; only the `a`
// operand needs a {a,a} broadcast mov.
// ============================================================================
__global__ __launch_bounds__(256) void main_kernel(
    const int* __restrict__ inp, const int* __restrict__ pos1, const int* __restrict__ pos2,
    const float* __restrict__ maskL, const float* __restrict__ maskM, const float* __restrict__ maskR,
    const float* __restrict__ word_emb, const float* __restrict__ pos_emb,
    const float* __restrict__ conv_b, float* __restrict__ out)
{
    extern __shared__ float sm[];
    float* sWt   = sm;                        // JB*128  = 3840 (16B aligned, first)
    float* sv    = sWt + JB * DC;             // 110*132 = 14520
    float* sMask = sv + CVAR * VSTRIDE;       // 3*128
    float* sBase = sMask + 3 * SEN;           // 3*128
    float* sCb   = sBase + 3 * DC;            // 128

    const int tid = threadIdx.x;
    const int b = blockIdx.x;
    const int lane = tid & 31, warp = tid >> 5;
    const int obase = warp * 16;

    // zero the v tile (covers the two padding columns 0 and 129)
    for (int i = tid; i < CVAR * VSTRIDE; i += 256) sv[i] = 0.f;

    for (int i = tid; i < 3 * SEN; i += 256) {
        float m = (i < 128) ? maskL[b * SEN + i]
                : (i < 256) ? maskM[b * SEN + i - 128]
                            : maskR[b * SEN + i - 256];
        sMask[i] = m;
        sBase[i] = gBase[(size_t)b * (3 * DC) + i];
    }
    if (tid < DC) sCb[tid] = conv_b[tid];
    __syncthreads();

    // gather word embeddings: v[c][s+1]
    const int* inpb = inp + b * SEN;
    for (int idx = tid; idx < SEN * 25; idx += 256) {
        int s = idx / 25, q = idx % 25;
        const float4 w4 = ((const float4*)word_emb)[inpb[s] * 25 + q];
        int c = q * 4;
        sv[(c + 0) * VSTRIDE + s + 1] = w4.x;
        sv[(c + 1) * VSTRIDE + s + 1] = w4.y;
        sv[(c + 2) * VSTRIDE + s + 1] = w4.z;
        sv[(c + 3) * VSTRIDE + s + 1] = w4.w;
    }
    // position embeddings: channels 100..109
    const int* p1b = pos1 + b * SEN;
    const int* p2b = pos2 + b * SEN;
    for (int idx = tid; idx < SEN * 10; idx += 256) {
        int s = idx / 10, q = idx % 10;
        int p = (q < 5) ? p1b[s] : p2b[s];
        int d = (q < 5) ? q : q - 5;
        sv[(100 + q) * VSTRIDE + s + 1] = pos_emb[p * 5 + d];
    }

    // ---- main GEMM with packed f32x2 FMAs ----
    u64 acc2[4][8];
    #pragma unroll
    for (int i = 0; i < 4; i++)
        #pragma unroll
        for (int p = 0; p < 8; p++) acc2[i][p] = 0ULL;

    for (int chunk = 0; chunk < J_TOT; chunk += JB) {
        __syncthreads();   // previous tile consumed (and, on iter 0, v fills done)
        {
            const float4* src = (const float4*)&gWr[chunk * DC];
            float4* dst = (float4*)sWt;
            for (int i = tid; i < JB * DC / 4; i += 256) dst[i] = src[i];
        }
        __syncthreads();
        #pragma unroll 6
        for (int jj = 0; jj < JB; jj++) {
            int j = chunk + jj;
            int k = (j >= 220) ? 2 : (j >= 110) ? 1 : 0;
            int c = j - k * CVAR;
            const float* vr = &sv[c * VSTRIDE + k + lane];
            float a0 = vr[0], a1 = vr[32], a2 = vr[64], a3 = vr[96];
            u64 aa[4];
            asm("mov.b64 %0, {%1, %1};" : "=l"(aa[0]) : "f"(a0));
            asm("mov.b64 %0, {%1, %1};" : "=l"(aa[1]) : "f"(a1));
            asm("mov.b64 %0, {%1, %1};" : "=l"(aa[2]) : "f"(a2));
            asm("mov.b64 %0, {%1, %1};" : "=l"(aa[3]) : "f"(a3));
            const ulonglong2* wp = (const ulonglong2*)&sWt[jj * DC + obase];
            ulonglong2 q0 = wp[0], q1 = wp[1], q2 = wp[2], q3 = wp[3];
            u64 wv[8] = {q0.x, q0.y, q1.x, q1.y, q2.x, q2.y, q3.x, q3.y};
            #pragma unroll
            for (int p = 0; p < 8; p++) {
                #pragma unroll
                for (int i = 0; i < 4; i++) {
                    asm("fma.rn.f32x2 %0, %1, %2, %0;"
                        : "+l"(acc2[i][p]) : "l"(aa[i]), "l"(wv[p]));
                }
            }
        }
    }

    // ---- epilogue: bias + edge-corrected base, masked max over s, tanh ----
    float mvL[4], mvM[4], mvR[4];
    #pragma unroll
    for (int i = 0; i < 4; i++) {
        int s = lane + 32 * i;
        mvL[i] = sMask[s];
        mvM[i] = sMask[128 + s];
        mvR[i] = sMask[256 + s];
    }
    float* outb = out + (size_t)b * OUTD;
    #pragma unroll
    for (int p = 0; p < 8; p++) {
        // unpack the two output channels held in this packed accumulator pair
        float av[2][4];
        #pragma unroll
        for (int i = 0; i < 4; i++) {
            float lo, hi;
            asm("mov.b64 {%0, %1}, %2;" : "=f"(lo), "=f"(hi) : "l"(acc2[i][p]));
            av[0][i] = lo;   // t = 2p
            av[1][i] = hi;   // t = 2p+1
        }
        #pragma unroll
        for (int h = 0; h < 2; h++) {
            int o = obase + 2 * p + h;
            float cb  = sCb[o];
            float bs0 = sBase[o], bs1 = sBase[128 + o], bs2 = sBase[256 + o];
            float pL = -1e30f, pM = -1e30f, pR = -1e30f;
            #pragma unroll
            for (int i = 0; i < 4; i++) {
                int s = lane + 32 * i;
                float cv = av[h][i] + cb + bs1;
                if (s > 0)   cv += bs0;   // k=0 tap valid only when s-1 >= 0
                if (s < 127) cv += bs2;   // k=2 tap valid only when s+1 <= 127
                pL = fmaxf(pL, cv * mvL[i]);
                pM = fmaxf(pM, cv * mvM[i]);
                pR = fmaxf(pR, cv * mvR[i]);
            }
            #pragma unroll
            for (int off = 16; off > 0; off >>= 1) {
                pL = fmaxf(pL, __shfl_xor_sync(0xffffffffu, pL, off));
                pM = fmaxf(pM, __shfl_xor_sync(0xffffffffu, pM, off));
                pR = fmaxf(pR, __shfl_xor_sync(0xffffffffu, pR, off));
            }
            if (lane == 0) {
                outb[o]       = tanhf(pL);
                outb[128 + o] = tanhf(pM);
                outb[256 + o] = tanhf(pR);
            }
        }
    }
}

// ============================================================================
extern "C" void kernel_launch(void* const* d_in, const int* in_sizes, int n_in,
                              void* d_out, int out_size) {
    const int*   inp       = (const int*)d_in[0];
    const int*   pos1      = (const int*)d_in[1];
    const int*   pos2      = (const int*)d_in[2];
    const int*   loc       = (const int*)d_in[3];
    const int*   loc_mark  = (const int*)d_in[4];
    const int*   subtype   = (const int*)d_in[5];
    const int*   argRole   = (const int*)d_in[6];
    const float* maskL     = (const float*)d_in[7];
    const float* maskM     = (const float*)d_in[8];
    const float* maskR     = (const float*)d_in[9];
    const float* word_emb  = (const float*)d_in[10];
    const float* pos_emb   = (const float*)d_in[11];
    const float* event_emb = (const float*)d_in[12];
    const float* role_emb  = (const float*)d_in[13];
    const float* conv_w    = (const float*)d_in[14];
    const float* conv_b    = (const float*)d_in[15];
    float* out = (float*)d_out;

    int prep_elems = J_TOT * DC + 3 * CCONST * DC;
    prep_kernel<<<(prep_elems + 255) / 256, 256>>>(conv_w);
    const_kernel<<<SZ / GS, 256>>>(loc, loc_mark, subtype, argRole,
                                   word_emb, event_emb, role_emb, out);
    size_t smem = (size_t)(JB * DC + CVAR * VSTRIDE + 3 * SEN + 3 * DC + DC) * sizeof(float);
    cudaFuncSetAttribute(main_kernel, cudaFuncAttributeMaxDynamicSharedMemorySize, (int)smem);
    main_kernel<<<SZ, 256, smem>>>(inp, pos1, pos2, maskL, maskM, maskR,
                                   word_emb, pos_emb, conv_b, out);
}

// round 5
// speedup vs baseline: 2.1729x; 1.8803x over previous
#include <cuda_runtime.h>
#include <math.h>
#include <stdint.h>

#define SZ     4096
#define SEN    128
#define DC     128
#define OUTD   984
#define CCONST 160
#define GS     8
#define KT     42            // k8 steps = 3 taps * 14
#define CK     6             // ksteps per cp.async chunk
#define NCH    7             // KT / CK
#define VROWS  112
#define VSTR   136           // (lane%4)*136 + lane>>2 -> conflict-free (136%32==8)
#define BF_CHUNK (CK*16*32*2)   // 6144 floats = 24KB per chunk

// SMEM float offsets
#define SMF_SV   0                       // 112*136 = 15232
#define SMF_W    15232                   // 2 * 6144 = 12288
#define SMF_MASK 27520                   // 3*128
#define SMF_C    27904                   // 128
#define SMF_B0   28032                   // 128
#define SMF_B2   28160                   // 128
#define SMF_R    28288                   // 3*128*4 = 1536
#define SMF_TOT  29824                   // floats -> 119296 bytes

typedef unsigned long long u64;

__device__ __align__(16) float gBf[KT * 16 * 32 * 2];   // B fragments, tf32
__device__ __align__(16) float gW2[3 * CCONST * DC];
__device__ __align__(16) float gBase[SZ * 3 * DC];

__device__ __forceinline__ uint32_t smem_u32(const void* p) {
    uint32_t a;
    asm("{ .reg .u64 t; cvta.to.shared.u64 t, %1; cvt.u32.u64 %0, t; }" : "=r"(a) : "l"(p));
    return a;
}
__device__ __forceinline__ float f2tf_f(float f) {
    uint32_t r; asm("cvt.rna.tf32.f32 %0, %1;" : "=r"(r) : "f"(f));
    return __uint_as_float(r);
}
#define CP16(dst_u32, src_ptr) \
    asm volatile("cp.async.cg.shared.global [%0], [%1], 16;" :: "r"(dst_u32), "l"(src_ptr) : "memory")
#define CP_COMMIT() asm volatile("cp.async.commit_group;" ::: "memory")
#define CP_WAIT(n)  asm volatile("cp.async.wait_group %0;" :: "n"(n) : "memory")
#define MMA_TF32(d, a, bx, by) \
    asm volatile("mma.sync.aligned.m16n8k8.row.col.f32.tf32.tf32.f32 " \
        "{%0,%1,%2,%3},{%4,%5,%6,%7},{%8,%9},{%0,%1,%2,%3};" \
        : "+f"(d[0]), "+f"(d[1]), "+f"(d[2]), "+f"(d[3]) \
        : "r"(a[0]), "r"(a[1]), "r"(a[2]), "r"(a[3]), "r"(bx), "r"(by))

// ============================================================================
// P0: build tf32 B fragments (exact mma.sync per-lane layout) + gW2.
// B frag (m16n8k8 tf32): b0 at (k=lane%4, n=lane>>2), b1 at (k=lane%4+4, n).
// j = kt*8 + k ; j -> tap = j/112, c = j%112 ; value 0 for pad c>=110.
// ============================================================================
__global__ void prep_kernel(const float* __restrict__ conv_w) {
    int idx = blockIdx.x * blockDim.x + threadIdx.x;
    if (idx < KT * 16 * 32) {
        int lane = idx & 31, nt = (idx >> 5) & 15, kt = idx >> 9;
        int o = nt * 8 + (lane >> 2);
        int j0 = kt * 8 + (lane & 3);
        float v0 = 0.f, v1 = 0.f;
        {
            int tap = j0 / 112, c = j0 % 112;
            if (c < 110) v0 = conv_w[o * 810 + c * 3 + tap];
        }
        {
            int j1 = j0 + 4;
            int tap = j1 / 112, c = j1 % 112;
            if (c < 110) v1 = conv_w[o * 810 + c * 3 + tap];
        }
        gBf[idx * 2 + 0] = f2tf_f(v0);
        gBf[idx * 2 + 1] = f2tf_f(v1);
    } else {
        int i2 = idx - KT * 16 * 32;
        if (i2 < 3 * CCONST * DC) {
            int kc = i2 / DC, o = i2 % DC;
            int k = kc / CCONST, c2 = kc % CCONST;
            gW2[i2] = conv_w[o * 810 + (110 + c2) * 3 + k];
        }
    }
}

// ============================================================================
// P1: constant-channel base + loc branch (exact fp32, unchanged).
// ============================================================================
__global__ __launch_bounds__(256) void const_kernel(
    const int* __restrict__ loc, const int* __restrict__ loc_mark,
    const int* __restrict__ subtype, const int* __restrict__ argRole,
    const float* __restrict__ word_emb, const float* __restrict__ event_emb,
    const float* __restrict__ role_emb, float* __restrict__ out)
{
    __shared__ float evrl[GS][CCONST];
    int tid = threadIdx.x;
    int b0 = blockIdx.x * GS;
    for (int i = tid; i < GS * CCONST; i += 256) {
        int g = i / CCONST, c2 = i % CCONST;
        int b = b0 + g;
        float v;
        if (c2 < 32) v = event_emb[subtype[b] * 32 + c2];
        else { int r = (c2 - 32) >> 4, q = (c2 - 32) & 15; v = role_emb[argRole[b * 8 + r] * 16 + q]; }
        evrl[g][c2] = v;
    }
    __syncthreads();
    for (int t = tid; t < 3 * DC; t += 256) {
        int o = t % DC, k = t / DC;
        float s[GS];
        #pragma unroll
        for (int g = 0; g < GS; g++) s[g] = 0.f;
        const float* w2 = &gW2[k * CCONST * DC + o];
        for (int c2 = 0; c2 < CCONST; c2++) {
            float w = w2[c2 * DC];
            #pragma unroll
            for (int g = 0; g < GS; g++) s[g] = fmaf(evrl[g][c2], w, s[g]);
        }
        #pragma unroll
        for (int g = 0; g < GS; g++) gBase[(size_t)(b0 + g) * (3 * DC) + t] = s[g];
    }
    int g = tid >> 5, lane = tid & 31;
    int b = b0 + g;
    const int* lb = &loc[b * 16];
    int mark = loc_mark[b];
    float* ob = &out[(size_t)b * OUTD + 384];
    for (int d = lane; d < 100; d += 32) {
        #pragma unroll
        for (int i = 0; i < 4; i++) ob[i * 100 + d] = tanhf(word_emb[lb[i] * 100 + d]);
        float s = 0.f;
        for (int i = 0; i < mark; i++) s += word_emb[lb[4 + i] * 100 + d];
        ob[400 + d] = tanhf(s / (float)mark);
        ob[500 + d] = tanhf(word_emb[lb[4 + mark] * 100 + d]);
    }
}

// ============================================================================
// Main: one CTA per sample. TF32 mma.sync GEMM (M=128 s, N=128 o, K=336),
// A in SMEM v-tile (tf32), B fragments streamed via double-buffered cp.async.
// Warp grid 4(M) x 2(N), warp tile m32 x n64.
// ============================================================================
__global__ __launch_bounds__(256, 1) void main_kernel(
    const int* __restrict__ inp, const int* __restrict__ pos1, const int* __restrict__ pos2,
    const float* __restrict__ maskL, const float* __restrict__ maskM, const float* __restrict__ maskR,
    const float* __restrict__ word_emb, const float* __restrict__ pos_emb,
    const float* __restrict__ conv_b, float* __restrict__ out)
{
    extern __shared__ float smf[];
    float* sv = smf + SMF_SV;
    uint32_t* svu = (uint32_t*)sv;
    float* sW = smf + SMF_W;
    float* sMask = smf + SMF_MASK;
    float* sC = smf + SMF_C;
    float* sB0 = smf + SMF_B0;
    float* sB2 = smf + SMF_B2;
    float* sR = smf + SMF_R;

    const int tid = threadIdx.x;
    const int lane = tid & 31, warp = tid >> 5;
    const int warp_m = warp & 3, warp_n = warp >> 2;
    const int b = blockIdx.x;

    // ---- kick off B chunk 0 immediately ----
    {
        const float* src = gBf;
        uint32_t dst = smem_u32(sW);
        for (int i = tid; i < BF_CHUNK / 4; i += 256)
            CP16(dst + i * 16, src + i * 4);
        CP_COMMIT();
    }

    // ---- zero v tile (pad cols/rows) ----
    for (int i = tid; i < VROWS * VSTR; i += 256) sv[i] = 0.f;

    // ---- stage masks / combined bias ----
    for (int i = tid; i < 3 * SEN; i += 256) {
        sMask[i] = (i < 128) ? maskL[b * SEN + i]
                 : (i < 256) ? maskM[b * SEN + i - 128]
                             : maskR[b * SEN + i - 256];
    }
    if (tid < DC) {
        float b0v = gBase[(size_t)b * 384 + tid];
        float b1v = gBase[(size_t)b * 384 + 128 + tid];
        float b2v = gBase[(size_t)b * 384 + 256 + tid];
        sC[tid] = conv_b[tid] + b0v + b1v + b2v;
        sB0[tid] = b0v;
        sB2[tid] = b2v;
    }
    __syncthreads();   // zeros visible before gather overwrites interior

    // ---- gather embeddings into v tile (tf32-rounded) ----
    const int* inpb = inp + b * SEN;
    for (int idx = tid; idx < SEN * 25; idx += 256) {
        int s = idx / 25, q = idx % 25;
        float4 w4 = ((const float4*)word_emb)[(size_t)inpb[s] * 25 + q];
        int c = q * 4;
        sv[(c + 0) * VSTR + s + 1] = f2tf_f(w4.x);
        sv[(c + 1) * VSTR + s + 1] = f2tf_f(w4.y);
        sv[(c + 2) * VSTR + s + 1] = f2tf_f(w4.z);
        sv[(c + 3) * VSTR + s + 1] = f2tf_f(w4.w);
    }
    const int* p1b = pos1 + b * SEN;
    const int* p2b = pos2 + b * SEN;
    for (int idx = tid; idx < SEN * 10; idx += 256) {
        int s = idx / 10, r = idx % 10;
        int row = (r < 5) ? p1b[s] : p2b[s];
        sv[(100 + r) * VSTR + s + 1] = f2tf_f(pos_emb[row * 5 + (r % 5)]);
    }

    // ---- GEMM main loop ----
    float acc[2][8][4];
    #pragma unroll
    for (int mt = 0; mt < 2; mt++)
        #pragma unroll
        for (int nt = 0; nt < 8; nt++)
            #pragma unroll
            for (int r = 0; r < 4; r++) acc[mt][nt][r] = 0.f;

    const int a_lane_base = (lane & 3) * VSTR + warp_m * 32 + (lane >> 2);

    for (int ch = 0; ch < NCH; ch++) {
        if (ch + 1 < NCH) {
            const float* src = gBf + (ch + 1) * BF_CHUNK;
            uint32_t dst = smem_u32(sW + ((ch + 1) & 1) * BF_CHUNK);
            for (int i = tid; i < BF_CHUNK / 4; i += 256)
                CP16(dst + i * 16, src + i * 4);
            CP_COMMIT();
            CP_WAIT(1);
        } else {
            CP_WAIT(0);
        }
        __syncthreads();   // chunk ch ready; also (ch==0) gathers done

        const float* wbuf = sW + (ch & 1) * BF_CHUNK;
        #pragma unroll
        for (int ktc = 0; ktc < CK; ktc++) {
            int kt = ch * CK + ktc;
            int tap = (kt >= 28) ? 2 : (kt >= 14) ? 1 : 0;
            int c0 = (kt - tap * 14) * 8;
            int ab = c0 * VSTR + tap + a_lane_base;
            uint32_t a0[4], a1[4];
            a0[0] = svu[ab];                a0[1] = svu[ab + 8];
            a0[2] = svu[ab + 4 * VSTR];     a0[3] = svu[ab + 4 * VSTR + 8];
            a1[0] = svu[ab + 16];           a1[1] = svu[ab + 24];
            a1[2] = svu[ab + 4 * VSTR + 16];a1[3] = svu[ab + 4 * VSTR + 24];
            const uint2* bw = (const uint2*)(wbuf + (ktc * 16 + warp_n * 8) * 64);
            #pragma unroll
            for (int nt = 0; nt < 8; nt++) {
                uint2 bb = bw[nt * 32 + lane];
                MMA_TF32(acc[0][nt], a0, bb.x, bb.y);
                MMA_TF32(acc[1][nt], a1, bb.x, bb.y);
            }
        }
        __syncthreads();   // all warps done with this buffer before reload
    }

    // ---- epilogue: edge-corrected masked max, cross-lane + cross-warp ----
    float mv[3][4];
    int srow[4];
    #pragma unroll
    for (int mt = 0; mt < 2; mt++)
        #pragma unroll
        for (int rg = 0; rg < 2; rg++) {
            int s = warp_m * 32 + mt * 16 + (lane >> 2) + rg * 8;
            int q = mt * 2 + rg;
            srow[q] = s;
            mv[0][q] = sMask[s];
            mv[1][q] = sMask[128 + s];
            mv[2][q] = sMask[256 + s];
        }

    #pragma unroll
    for (int nt = 0; nt < 8; nt++) {
        #pragma unroll
        for (int h = 0; h < 2; h++) {
            int o = warp_n * 64 + nt * 8 + 2 * (lane & 3) + h;
            float C = sC[o], B0v = sB0[o], B2v = sB2[o];
            float p0 = -3.0e38f, p1 = -3.0e38f, p2 = -3.0e38f;
            #pragma unroll
            for (int mt = 0; mt < 2; mt++)
                #pragma unroll
                for (int rg = 0; rg < 2; rg++) {
                    int q = mt * 2 + rg;
                    int s = srow[q];
                    float cv = acc[mt][nt][rg * 2 + h] + C;
                    if (s == 0)   cv -= B0v;
                    if (s == 127) cv -= B2v;
                    p0 = fmaxf(p0, cv * mv[0][q]);
                    p1 = fmaxf(p1, cv * mv[1][q]);
                    p2 = fmaxf(p2, cv * mv[2][q]);
                }
            #pragma unroll
            for (int off = 4; off <= 16; off <<= 1) {
                p0 = fmaxf(p0, __shfl_xor_sync(0xffffffffu, p0, off));
                p1 = fmaxf(p1, __shfl_xor_sync(0xffffffffu, p1, off));
                p2 = fmaxf(p2, __shfl_xor_sync(0xffffffffu, p2, off));
            }
            if ((lane & 28) == 0) {   // lane 0..3
                sR[((0 * 128 + o) << 2) + warp_m] = p0;
                sR[((1 * 128 + o) << 2) + warp_m] = p1;
                sR[((2 * 128 + o) << 2) + warp_m] = p2;
            }
        }
    }
    __syncthreads();

    for (int t = tid; t < 384; t += 256) {
        const float* rp = &sR[t << 2];
        float R = fmaxf(fmaxf(rp[0], rp[1]), fmaxf(rp[2], rp[3]));
        out[(size_t)b * OUTD + t] = tanhf(R);
    }
}

// ============================================================================
extern "C" void kernel_launch(void* const* d_in, const int* in_sizes, int n_in,
                              void* d_out, int out_size) {
    const int*   inp       = (const int*)d_in[0];
    const int*   pos1      = (const int*)d_in[1];
    const int*   pos2      = (const int*)d_in[2];
    const int*   loc       = (const int*)d_in[3];
    const int*   loc_mark  = (const int*)d_in[4];
    const int*   subtype   = (const int*)d_in[5];
    const int*   argRole   = (const int*)d_in[6];
    const float* maskL     = (const float*)d_in[7];
    const float* maskM     = (const float*)d_in[8];
    const float* maskR     = (const float*)d_in[9];
    const float* word_emb  = (const float*)d_in[10];
    const float* pos_emb   = (const float*)d_in[11];
    const float* event_emb = (const float*)d_in[12];
    const float* role_emb  = (const float*)d_in[13];
    const float* conv_w    = (const float*)d_in[14];
    const float* conv_b    = (const float*)d_in[15];
    float* out = (float*)d_out;

    int prep_elems = KT * 16 * 32 + 3 * CCONST * DC;
    prep_kernel<<<(prep_elems + 255) / 256, 256>>>(conv_w);
    const_kernel<<<SZ / GS, 256>>>(loc, loc_mark, subtype, argRole,
                                   word_emb, event_emb, role_emb, out);
    size_t smem = (size_t)SMF_TOT * sizeof(float);
    cudaFuncSetAttribute(main_kernel, cudaFuncAttributeMaxDynamicSharedMemorySize, (int)smem);
    main_kernel<<<SZ, 256, smem>>>(inp, pos1, pos2, maskL, maskM, maskR,
                                   word_emb, pos_emb, conv_b, out);
}

// round 6
// speedup vs baseline: 4.0558x; 1.8665x over previous
#include <cuda_runtime.h>
#include <cuda_fp16.h>
#include <math.h>
#include <stdint.h>

#define SZ     4096
#define SEN    128
#define DC     128
#define OUTD   984
#define CCONST 160
#define GS     8
#define KT     21             // k16 steps = 3 taps * 7
#define VSTR2  136            // half2-word stride: (q)*136 + x, 136%32==8 -> conflict-free
#define NQ     56             // 112 channels / 2 per half2

// SMEM byte offsets
#define SMB_B    0             // 21*16*32*2 u32 = 86016 B
#define SMB_VH   86016         // 56*136 half2 = 30464 B
#define SMB_MASK 116480        // 384 f
#define SMB_C    118016        // 128 f
#define SMB_B0   118528
#define SMB_B2   119040
#define SMB_R    119552        // 3*128*4 f = 6144 B
#define SMB_TOT  125696

typedef unsigned long long u64;

__device__ __align__(16) uint32_t gBfh[KT * 16 * 32 * 2];   // fp16 B fragments
__device__ __align__(16) float gW2[3 * CCONST * DC];
__device__ __align__(16) float gBase[SZ * 3 * DC];

__device__ __forceinline__ uint32_t smem_u32(const void* p) {
    uint32_t a;
    asm("{ .reg .u64 t; cvta.to.shared.u64 t, %1; cvt.u32.u64 %0, t; }" : "=r"(a) : "l"(p));
    return a;
}
#define CP16(dst_u32, src_ptr) \
    asm volatile("cp.async.cg.shared.global [%0], [%1], 16;" :: "r"(dst_u32), "l"(src_ptr) : "memory")
#define CP_COMMIT() asm volatile("cp.async.commit_group;" ::: "memory")
#define CP_WAIT0()  asm volatile("cp.async.wait_group 0;" ::: "memory")
#define MMA_F16(d, a0, a1, a2, a3, bx, by) \
    asm volatile("mma.sync.aligned.m16n8k16.row.col.f32.f16.f16.f32 " \
        "{%0,%1,%2,%3},{%4,%5,%6,%7},{%8,%9},{%0,%1,%2,%3};" \
        : "+f"(d[0]), "+f"(d[1]), "+f"(d[2]), "+f"(d[3]) \
        : "r"(a0), "r"(a1), "r"(a2), "r"(a3), "r"(bx), "r"(by))

// ============================================================================
// P0: build fp16 B fragments (exact m16n8k16 per-lane layout) + gW2.
// Per u32: idx = ((kt*16+nt)*32+lane)*2 + r ; halves at k=(lane&3)*2+r*8 +{0,1},
// n = o = nt*8 + lane>>2 ; j = kt*16 + k -> tap=j/112, c=j%112 (0 for c>=110).
// ============================================================================
__global__ void prep_kernel(const float* __restrict__ conv_w) {
    int idx = blockIdx.x * blockDim.x + threadIdx.x;
    if (idx < KT * 16 * 32 * 2) {
        int r = idx & 1, lane = (idx >> 1) & 31, nt = (idx >> 6) & 15, kt = idx >> 10;
        int o = nt * 8 + (lane >> 2);
        int j0 = kt * 16 + (lane & 3) * 2 + r * 8;
        float v0 = 0.f, v1 = 0.f;
        { int tap = j0 / 112, c = j0 % 112; if (c < 110) v0 = conv_w[o * 810 + c * 3 + tap]; }
        { int j1 = j0 + 1; int tap = j1 / 112, c = j1 % 112; if (c < 110) v1 = conv_w[o * 810 + c * 3 + tap]; }
        __half2 h = __floats2half2_rn(v0, v1);
        gBfh[idx] = *(uint32_t*)&h;
    } else {
        int i2 = idx - KT * 16 * 32 * 2;
        if (i2 < 3 * CCONST * DC) {
            int kc = i2 / DC, o = i2 % DC;
            int k = kc / CCONST, c2 = kc % CCONST;
            gW2[i2] = conv_w[o * 810 + (110 + c2) * 3 + k];
        }
    }
}

// ============================================================================
// P1: constant-channel base + loc branch (exact fp32, unchanged).
// ============================================================================
__global__ __launch_bounds__(256) void const_kernel(
    const int* __restrict__ loc, const int* __restrict__ loc_mark,
    const int* __restrict__ subtype, const int* __restrict__ argRole,
    const float* __restrict__ word_emb, const float* __restrict__ event_emb,
    const float* __restrict__ role_emb, float* __restrict__ out)
{
    __shared__ float evrl[GS][CCONST];
    int tid = threadIdx.x;
    int b0 = blockIdx.x * GS;
    for (int i = tid; i < GS * CCONST; i += 256) {
        int g = i / CCONST, c2 = i % CCONST;
        int b = b0 + g;
        float v;
        if (c2 < 32) v = event_emb[subtype[b] * 32 + c2];
        else { int r = (c2 - 32) >> 4, q = (c2 - 32) & 15; v = role_emb[argRole[b * 8 + r] * 16 + q]; }
        evrl[g][c2] = v;
    }
    __syncthreads();
    for (int t = tid; t < 3 * DC; t += 256) {
        int o = t % DC, k = t / DC;
        float s[GS];
        #pragma unroll
        for (int g = 0; g < GS; g++) s[g] = 0.f;
        const float* w2 = &gW2[k * CCONST * DC + o];
        for (int c2 = 0; c2 < CCONST; c2++) {
            float w = w2[c2 * DC];
            #pragma unroll
            for (int g = 0; g < GS; g++) s[g] = fmaf(evrl[g][c2], w, s[g]);
        }
        #pragma unroll
        for (int g = 0; g < GS; g++) gBase[(size_t)(b0 + g) * (3 * DC) + t] = s[g];
    }
    int g = tid >> 5, lane = tid & 31;
    int b = b0 + g;
    const int* lb = &loc[b * 16];
    int mark = loc_mark[b];
    float* ob = &out[(size_t)b * OUTD + 384];
    for (int d = lane; d < 100; d += 32) {
        #pragma unroll
        for (int i = 0; i < 4; i++) ob[i * 100 + d] = tanhf(word_emb[lb[i] * 100 + d]);
        float s = 0.f;
        for (int i = 0; i < mark; i++) s += word_emb[lb[4 + i] * 100 + d];
        ob[400 + d] = tanhf(s / (float)mark);
        ob[500 + d] = tanhf(word_emb[lb[4 + mark] * 100 + d]);
    }
}

// ============================================================================
// Main: one CTA (512 thr) per sample. FP16 m16n8k16 mma.sync GEMM
// (M=128 s, N=128 o, K=336). B fully SMEM-resident (one cp.async burst,
// overlapped with gather). A tile in half2 pairs [q][x], x = s+tap.
// Warp grid 4(M) x 4(N); warp tile m32 x n32; zero syncs in mainloop.
// ============================================================================
__global__ __launch_bounds__(512, 1) void main_kernel(
    const int* __restrict__ inp, const int* __restrict__ pos1, const int* __restrict__ pos2,
    const float* __restrict__ maskL, const float* __restrict__ maskM, const float* __restrict__ maskR,
    const float* __restrict__ word_emb, const float* __restrict__ pos_emb,
    const float* __restrict__ conv_b, float* __restrict__ out)
{
    extern __shared__ char smb[];
    uint32_t* sB   = (uint32_t*)(smb + SMB_B);
    uint32_t* svu  = (uint32_t*)(smb + SMB_VH);     // half2 words
    __half2*  vh2  = (__half2*)(smb + SMB_VH);
    __half*   vh   = (__half*)(smb + SMB_VH);
    float* sMask = (float*)(smb + SMB_MASK);
    float* sC    = (float*)(smb + SMB_C);
    float* sB0   = (float*)(smb + SMB_B0);
    float* sB2   = (float*)(smb + SMB_B2);
    float* sR    = (float*)(smb + SMB_R);

    const int tid = threadIdx.x;
    const int lane = tid & 31, warp = tid >> 5;
    const int warp_m = warp & 3, warp_n = warp >> 2;   // 4 x 4
    const int b = blockIdx.x;

    // ---- kick off the full B load (84KB) ----
    {
        uint32_t dst = smem_u32(sB);
        const uint32_t* src = gBfh;
        for (int i = tid; i < KT * 16 * 32 * 2 / 4; i += 512)
            CP16(dst + i * 16, src + i * 4);
        CP_COMMIT();
    }

    // ---- zero vh tile (covers pad pair q=55 and edge cols 0/129) ----
    for (int i = tid; i < NQ * VSTR2; i += 512) svu[i] = 0u;

    // ---- stage masks / combined bias ----
    for (int i = tid; i < 3 * SEN; i += 512) {
        sMask[i] = (i < 128) ? maskL[b * SEN + i]
                 : (i < 256) ? maskM[b * SEN + i - 128]
                             : maskR[b * SEN + i - 256];
    }
    if (tid < DC) {
        float b0v = gBase[(size_t)b * 384 + tid];
        float b1v = gBase[(size_t)b * 384 + 128 + tid];
        float b2v = gBase[(size_t)b * 384 + 256 + tid];
        sC[tid] = conv_b[tid] + b0v + b1v + b2v;
        sB0[tid] = b0v;
        sB2[tid] = b2v;
    }
    __syncthreads();   // zeros visible before gather overwrites interior

    // ---- gather embeddings (fp16) ; channel c at position p -> vh[q][p+1] ----
    const int* inpb = inp + b * SEN;
    for (int idx = tid; idx < SEN * 25; idx += 512) {
        int s = idx / 25, q4 = idx % 25;
        float4 w4 = ((const float4*)word_emb)[(size_t)inpb[s] * 25 + q4];
        vh2[(2 * q4 + 0) * VSTR2 + s + 1] = __floats2half2_rn(w4.x, w4.y);
        vh2[(2 * q4 + 1) * VSTR2 + s + 1] = __floats2half2_rn(w4.z, w4.w);
    }
    const int* p1b = pos1 + b * SEN;
    const int* p2b = pos2 + b * SEN;
    for (int idx = tid; idx < SEN * 10; idx += 512) {
        int s = idx / 10, r = idx % 10;
        int row = (r < 5) ? p1b[s] : p2b[s];
        int c = 100 + r;
        vh[(c >> 1) * (2 * VSTR2) + (s + 1) * 2 + (c & 1)] =
            __float2half_rn(pos_emb[row * 5 + (r % 5)]);
    }

    CP_WAIT0();
    __syncthreads();   // B resident + vh complete

    // ---- GEMM mainloop: 3 taps x 7 ksteps, no syncs ----
    float acc[2][4][4];
    #pragma unroll
    for (int mt = 0; mt < 2; mt++)
        #pragma unroll
        for (int nt = 0; nt < 4; nt++)
            #pragma unroll
            for (int r = 0; r < 4; r++) acc[mt][nt][r] = 0.f;

    const int a_base = (lane & 3) * VSTR2 + warp_m * 32 + (lane >> 2);

    #pragma unroll
    for (int tap = 0; tap < 3; tap++) {
        #pragma unroll
        for (int ktl = 0; ktl < 7; ktl++) {
            const int kt = tap * 7 + ktl;
            const int ab = ktl * 8 * VSTR2 + tap + a_base;
            uint32_t am[2][4];
            #pragma unroll
            for (int mt = 0; mt < 2; mt++) {
                int o16 = mt * 16;
                am[mt][0] = svu[ab + o16];
                am[mt][1] = svu[ab + o16 + 8];
                am[mt][2] = svu[ab + o16 + 4 * VSTR2];
                am[mt][3] = svu[ab + o16 + 4 * VSTR2 + 8];
            }
            const uint2* bw = (const uint2*)(sB + kt * 1024);
            #pragma unroll
            for (int nt = 0; nt < 4; nt++) {
                uint2 bb = bw[(warp_n * 4 + nt) * 32 + lane];
                MMA_F16(acc[0][nt], am[0][0], am[0][1], am[0][2], am[0][3], bb.x, bb.y);
                MMA_F16(acc[1][nt], am[1][0], am[1][1], am[1][2], am[1][3], bb.x, bb.y);
            }
        }
    }

    // ---- epilogue: edge-corrected masked max, cross-lane + cross-warp ----
    float mv[3][4];
    int srow[4];
    #pragma unroll
    for (int mt = 0; mt < 2; mt++)
        #pragma unroll
        for (int rg = 0; rg < 2; rg++) {
            int s = warp_m * 32 + mt * 16 + (lane >> 2) + rg * 8;
            int q = mt * 2 + rg;
            srow[q] = s;
            mv[0][q] = sMask[s];
            mv[1][q] = sMask[128 + s];
            mv[2][q] = sMask[256 + s];
        }

    #pragma unroll
    for (int nt = 0; nt < 4; nt++) {
        #pragma unroll
        for (int h = 0; h < 2; h++) {
            int o = warp_n * 32 + nt * 8 + 2 * (lane & 3) + h;
            float C = sC[o], B0v = sB0[o], B2v = sB2[o];
            float p0 = -3.0e38f, p1 = -3.0e38f, p2 = -3.0e38f;
            #pragma unroll
            for (int mt = 0; mt < 2; mt++)
                #pragma unroll
                for (int rg = 0; rg < 2; rg++) {
                    int q = mt * 2 + rg;
                    int s = srow[q];
                    float cv = acc[mt][nt][rg * 2 + h] + C;
                    if (s == 0)   cv -= B0v;
                    if (s == 127) cv -= B2v;
                    p0 = fmaxf(p0, cv * mv[0][q]);
                    p1 = fmaxf(p1, cv * mv[1][q]);
                    p2 = fmaxf(p2, cv * mv[2][q]);
                }
            #pragma unroll
            for (int off = 4; off <= 16; off <<= 1) {
                p0 = fmaxf(p0, __shfl_xor_sync(0xffffffffu, p0, off));
                p1 = fmaxf(p1, __shfl_xor_sync(0xffffffffu, p1, off));
                p2 = fmaxf(p2, __shfl_xor_sync(0xffffffffu, p2, off));
            }
            if ((lane & 28) == 0) {   // lanes 0..3 hold the 4 warp_m partials
                sR[((0 * 128 + o) << 2) + warp_m] = p0;
                sR[((1 * 128 + o) << 2) + warp_m] = p1;
                sR[((2 * 128 + o) << 2) + warp_m] = p2;
            }
        }
    }
    __syncthreads();

    for (int t = tid; t < 384; t += 512) {
        const float* rp = &sR[t << 2];
        float R = fmaxf(fmaxf(rp[0], rp[1]), fmaxf(rp[2], rp[3]));
        out[(size_t)b * OUTD + t] = tanhf(R);
    }
}

// ============================================================================
extern "C" void kernel_launch(void* const* d_in, const int* in_sizes, int n_in,
                              void* d_out, int out_size) {
    const int*   inp       = (const int*)d_in[0];
    const int*   pos1      = (const int*)d_in[1];
    const int*   pos2      = (const int*)d_in[2];
    const int*   loc       = (const int*)d_in[3];
    const int*   loc_mark  = (const int*)d_in[4];
    const int*   subtype   = (const int*)d_in[5];
    const int*   argRole   = (const int*)d_in[6];
    const float* maskL     = (const float*)d_in[7];
    const float* maskM     = (const float*)d_in[8];
    const float* maskR     = (const float*)d_in[9];
    const float* word_emb  = (const float*)d_in[10];
    const float* pos_emb   = (const float*)d_in[11];
    const float* event_emb = (const float*)d_in[12];
    const float* role_emb  = (const float*)d_in[13];
    const float* conv_w    = (const float*)d_in[14];
    const float* conv_b    = (const float*)d_in[15];
    float* out = (float*)d_out;

    int prep_elems = KT * 16 * 32 * 2 + 3 * CCONST * DC;
    prep_kernel<<<(prep_elems + 255) / 256, 256>>>(conv_w);
    const_kernel<<<SZ / GS, 256>>>(loc, loc_mark, subtype, argRole,
                                   word_emb, event_emb, role_emb, out);
    cudaFuncSetAttribute(main_kernel, cudaFuncAttributeMaxDynamicSharedMemorySize, SMB_TOT);
    main_kernel<<<SZ, 512, SMB_TOT>>>(inp, pos1, pos2, maskL, maskM, maskR,
                                      word_emb, pos_emb, conv_b, out);
}

// round 7
// speedup vs baseline: 4.7382x; 1.1683x over previous
#include <cuda_runtime.h>
#include <cuda_fp16.h>
#include <math.h>
#include <stdint.h>

#define SZ     4096
#define SEN    128
#define DC     128
#define OUTD   984
#define CCONST 160
#define GS     8
#define KT     21             // k16 steps = 3 taps * 7
#define VSTR2  136            // half2-word stride (136%32==8 -> conflict-free)
#define NQ     56             // 112 channels / 2 per half2
#define VH_BYTES (NQ * VSTR2 * 4)   // 30464 per sample

// SMEM byte offsets
#define SMB_B    0             // 21*16*32*2 u32 = 86016
#define SMB_VH   86016         // 2 * 30464 = 60928
#define SMB_MASK 146944        // 2*384 f = 3072
#define SMB_C    150016        // 2*128 f = 1024
#define SMB_B0   151040        // 1024
#define SMB_B2   152064        // 1024
#define SMB_R    153088        // 2*384*4 f = 12288
#define SMB_TOT  165376

typedef unsigned long long u64;

__device__ __align__(16) uint32_t gBfh[KT * 16 * 32 * 2];   // fp16 B fragments
__device__ __align__(16) float gW2[3 * CCONST * DC];
__device__ __align__(16) float gBase[SZ * 3 * DC];

__device__ __forceinline__ uint32_t smem_u32(const void* p) {
    uint32_t a;
    asm("{ .reg .u64 t; cvta.to.shared.u64 t, %1; cvt.u32.u64 %0, t; }" : "=r"(a) : "l"(p));
    return a;
}
#define CP16(dst_u32, src_ptr) \
    asm volatile("cp.async.cg.shared.global [%0], [%1], 16;" :: "r"(dst_u32), "l"(src_ptr) : "memory")
#define CP_COMMIT() asm volatile("cp.async.commit_group;" ::: "memory")
#define CP_WAIT0()  asm volatile("cp.async.wait_group 0;" ::: "memory")
#define MMA_F16(d, a0, a1, a2, a3, bx, by) \
    asm volatile("mma.sync.aligned.m16n8k16.row.col.f32.f16.f16.f32 " \
        "{%0,%1,%2,%3},{%4,%5,%6,%7},{%8,%9},{%0,%1,%2,%3};" \
        : "+f"(d[0]), "+f"(d[1]), "+f"(d[2]), "+f"(d[3]) \
        : "r"(a0), "r"(a1), "r"(a2), "r"(a3), "r"(bx), "r"(by))

// ============================================================================
// P0: fp16 B fragments (exact m16n8k16 per-lane layout) + gW2. (unchanged)
// ============================================================================
__global__ void prep_kernel(const float* __restrict__ conv_w) {
    int idx = blockIdx.x * blockDim.x + threadIdx.x;
    if (idx < KT * 16 * 32 * 2) {
        int r = idx & 1, lane = (idx >> 1) & 31, nt = (idx >> 6) & 15, kt = idx >> 10;
        int o = nt * 8 + (lane >> 2);
        int j0 = kt * 16 + (lane & 3) * 2 + r * 8;
        float v0 = 0.f, v1 = 0.f;
        { int tap = j0 / 112, c = j0 % 112; if (c < 110) v0 = conv_w[o * 810 + c * 3 + tap]; }
        { int j1 = j0 + 1; int tap = j1 / 112, c = j1 % 112; if (c < 110) v1 = conv_w[o * 810 + c * 3 + tap]; }
        __half2 h = __floats2half2_rn(v0, v1);
        gBfh[idx] = *(uint32_t*)&h;
    } else {
        int i2 = idx - KT * 16 * 32 * 2;
        if (i2 < 3 * CCONST * DC) {
            int kc = i2 / DC, o = i2 % DC;
            int k = kc / CCONST, c2 = kc % CCONST;
            gW2[i2] = conv_w[o * 810 + (110 + c2) * 3 + k];
        }
    }
}

// ============================================================================
// P1: constant-channel base + loc branch (exact fp32, unchanged).
// ============================================================================
__global__ __launch_bounds__(256) void const_kernel(
    const int* __restrict__ loc, const int* __restrict__ loc_mark,
    const int* __restrict__ subtype, const int* __restrict__ argRole,
    const float* __restrict__ word_emb, const float* __restrict__ event_emb,
    const float* __restrict__ role_emb, float* __restrict__ out)
{
    __shared__ float evrl[GS][CCONST];
    int tid = threadIdx.x;
    int b0 = blockIdx.x * GS;
    for (int i = tid; i < GS * CCONST; i += 256) {
        int g = i / CCONST, c2 = i % CCONST;
        int b = b0 + g;
        float v;
        if (c2 < 32) v = event_emb[subtype[b] * 32 + c2];
        else { int r = (c2 - 32) >> 4, q = (c2 - 32) & 15; v = role_emb[argRole[b * 8 + r] * 16 + q]; }
        evrl[g][c2] = v;
    }
    __syncthreads();
    for (int t = tid; t < 3 * DC; t += 256) {
        int o = t % DC, k = t / DC;
        float s[GS];
        #pragma unroll
        for (int g = 0; g < GS; g++) s[g] = 0.f;
        const float* w2 = &gW2[k * CCONST * DC + o];
        for (int c2 = 0; c2 < CCONST; c2++) {
            float w = w2[c2 * DC];
            #pragma unroll
            for (int g = 0; g < GS; g++) s[g] = fmaf(evrl[g][c2], w, s[g]);
        }
        #pragma unroll
        for (int g = 0; g < GS; g++) gBase[(size_t)(b0 + g) * (3 * DC) + t] = s[g];
    }
    int g = tid >> 5, lane = tid & 31;
    int b = b0 + g;
    const int* lb = &loc[b * 16];
    int mark = loc_mark[b];
    float* ob = &out[(size_t)b * OUTD + 384];
    for (int d = lane; d < 100; d += 32) {
        #pragma unroll
        for (int i = 0; i < 4; i++) ob[i * 100 + d] = tanhf(word_emb[lb[i] * 100 + d]);
        float s = 0.f;
        for (int i = 0; i < mark; i++) s += word_emb[lb[4 + i] * 100 + d];
        ob[400 + d] = tanhf(s / (float)mark);
        ob[500 + d] = tanhf(word_emb[lb[4 + mark] * 100 + d]);
    }
}

// ============================================================================
// Main: 148 persistent CTAs (512 thr). B resident for kernel lifetime;
// 2 samples per iteration (each B fragment feeds 4 m-tiles).
// Warp grid 4(M) x 4(N); per sample warp tile m32 x n32.
// ============================================================================
__global__ __launch_bounds__(512, 1) void main_kernel(
    const int* __restrict__ inp, const int* __restrict__ pos1, const int* __restrict__ pos2,
    const float* __restrict__ maskL, const float* __restrict__ maskM, const float* __restrict__ maskR,
    const float* __restrict__ word_emb, const float* __restrict__ pos_emb,
    const float* __restrict__ conv_b, float* __restrict__ out)
{
    extern __shared__ char smb[];
    uint32_t* sB    = (uint32_t*)(smb + SMB_B);
    float* sMask = (float*)(smb + SMB_MASK);   // [sm][3*128]
    float* sC    = (float*)(smb + SMB_C);      // [sm][128]
    float* sB0   = (float*)(smb + SMB_B0);
    float* sB2   = (float*)(smb + SMB_B2);
    float* sR    = (float*)(smb + SMB_R);      // [sm][384][4]

    const int tid = threadIdx.x;
    const int lane = tid & 31, warp = tid >> 5;
    const int warp_m = warp & 3, warp_n = warp >> 2;

    // ---- one-time: load B (84KB) and zero both v tiles ----
    {
        uint32_t dst = smem_u32(sB);
        const uint32_t* src = gBfh;
        for (int i = tid; i < KT * 16 * 32 * 2 / 4; i += 512)
            CP16(dst + i * 16, src + i * 4);
        CP_COMMIT();
    }
    for (int i = tid; i < 2 * NQ * VSTR2; i += 512)
        ((uint32_t*)(smb + SMB_VH))[i] = 0u;
    CP_WAIT0();
    __syncthreads();

    const int a_base = (lane & 3) * VSTR2 + warp_m * 32 + (lane >> 2);

    for (int p = blockIdx.x; p < SZ / 2; p += gridDim.x) {
        const int bs[2] = { 2 * p, 2 * p + 1 };
        __syncthreads();   // previous iteration's epilogue fully consumed

        // ---- per-sample staging: masks, bias, gather ----
        #pragma unroll
        for (int sm = 0; sm < 2; sm++) {
            const int b = bs[sm];
            for (int i = tid; i < 3 * SEN; i += 512) {
                sMask[sm * 384 + i] =
                      (i < 128) ? maskL[b * SEN + i]
                    : (i < 256) ? maskM[b * SEN + i - 128]
                                : maskR[b * SEN + i - 256];
            }
            if (tid < DC) {
                float b0v = gBase[(size_t)b * 384 + tid];
                float b1v = gBase[(size_t)b * 384 + 128 + tid];
                float b2v = gBase[(size_t)b * 384 + 256 + tid];
                sC[sm * 128 + tid] = conv_b[tid] + b0v + b1v + b2v;
                sB0[sm * 128 + tid] = b0v;
                sB2[sm * 128 + tid] = b2v;
            }
            __half2* vh2 = (__half2*)(smb + SMB_VH + sm * VH_BYTES);
            __half*  vh  = (__half*)(smb + SMB_VH + sm * VH_BYTES);
            const int* inpb = inp + b * SEN;
            for (int idx = tid; idx < SEN * 25; idx += 512) {
                int s = idx / 25, q4 = idx % 25;
                float4 w4 = ((const float4*)word_emb)[(size_t)inpb[s] * 25 + q4];
                vh2[(2 * q4 + 0) * VSTR2 + s + 1] = __floats2half2_rn(w4.x, w4.y);
                vh2[(2 * q4 + 1) * VSTR2 + s + 1] = __floats2half2_rn(w4.z, w4.w);
            }
            const int* p1b = pos1 + b * SEN;
            const int* p2b = pos2 + b * SEN;
            for (int idx = tid; idx < SEN * 10; idx += 512) {
                int s = idx / 10, r = idx % 10;
                int row = (r < 5) ? p1b[s] : p2b[s];
                int c = 100 + r;
                vh[(c >> 1) * (2 * VSTR2) + (s + 1) * 2 + (c & 1)] =
                    __float2half_rn(pos_emb[row * 5 + (r % 5)]);
            }
        }
        __syncthreads();

        // ---- GEMM mainloop: both samples share each B fragment ----
        float acc[2][2][4][4];
        #pragma unroll
        for (int sm = 0; sm < 2; sm++)
            #pragma unroll
            for (int mt = 0; mt < 2; mt++)
                #pragma unroll
                for (int nt = 0; nt < 4; nt++)
                    #pragma unroll
                    for (int r = 0; r < 4; r++) acc[sm][mt][nt][r] = 0.f;

        const uint32_t* svu0 = (const uint32_t*)(smb + SMB_VH);
        const uint32_t* svu1 = (const uint32_t*)(smb + SMB_VH + VH_BYTES);

        #pragma unroll
        for (int tap = 0; tap < 3; tap++) {
            #pragma unroll
            for (int ktl = 0; ktl < 7; ktl++) {
                const int kt = tap * 7 + ktl;
                const int ab = ktl * 8 * VSTR2 + tap + a_base;
                uint32_t am[2][2][4];
                #pragma unroll
                for (int mt = 0; mt < 2; mt++) {
                    int o16 = mt * 16;
                    am[0][mt][0] = svu0[ab + o16];
                    am[0][mt][1] = svu0[ab + o16 + 8];
                    am[0][mt][2] = svu0[ab + o16 + 4 * VSTR2];
                    am[0][mt][3] = svu0[ab + o16 + 4 * VSTR2 + 8];
                    am[1][mt][0] = svu1[ab + o16];
                    am[1][mt][1] = svu1[ab + o16 + 8];
                    am[1][mt][2] = svu1[ab + o16 + 4 * VSTR2];
                    am[1][mt][3] = svu1[ab + o16 + 4 * VSTR2 + 8];
                }
                const uint2* bw = (const uint2*)(sB + kt * 1024);
                #pragma unroll
                for (int nt = 0; nt < 4; nt++) {
                    uint2 bb = bw[(warp_n * 4 + nt) * 32 + lane];
                    MMA_F16(acc[0][0][nt], am[0][0][0], am[0][0][1], am[0][0][2], am[0][0][3], bb.x, bb.y);
                    MMA_F16(acc[0][1][nt], am[0][1][0], am[0][1][1], am[0][1][2], am[0][1][3], bb.x, bb.y);
                    MMA_F16(acc[1][0][nt], am[1][0][0], am[1][0][1], am[1][0][2], am[1][0][3], bb.x, bb.y);
                    MMA_F16(acc[1][1][nt], am[1][1][0], am[1][1][1], am[1][1][2], am[1][1][3], bb.x, bb.y);
                }
            }
        }

        // ---- epilogue per sample ----
        #pragma unroll
        for (int sm = 0; sm < 2; sm++) {
            float mv[3][4];
            int srow[4];
            #pragma unroll
            for (int mt = 0; mt < 2; mt++)
                #pragma unroll
                for (int rg = 0; rg < 2; rg++) {
                    int s = warp_m * 32 + mt * 16 + (lane >> 2) + rg * 8;
                    int q = mt * 2 + rg;
                    srow[q] = s;
                    mv[0][q] = sMask[sm * 384 + s];
                    mv[1][q] = sMask[sm * 384 + 128 + s];
                    mv[2][q] = sMask[sm * 384 + 256 + s];
                }
            #pragma unroll
            for (int nt = 0; nt < 4; nt++) {
                #pragma unroll
                for (int h = 0; h < 2; h++) {
                    int o = warp_n * 32 + nt * 8 + 2 * (lane & 3) + h;
                    float C = sC[sm * 128 + o];
                    float B0v = sB0[sm * 128 + o], B2v = sB2[sm * 128 + o];
                    float p0 = -3.0e38f, p1 = -3.0e38f, p2 = -3.0e38f;
                    #pragma unroll
                    for (int mt = 0; mt < 2; mt++)
                        #pragma unroll
                        for (int rg = 0; rg < 2; rg++) {
                            int q = mt * 2 + rg;
                            int s = srow[q];
                            float cv = acc[sm][mt][nt][rg * 2 + h] + C;
                            if (s == 0)   cv -= B0v;
                            if (s == 127) cv -= B2v;
                            p0 = fmaxf(p0, cv * mv[0][q]);
                            p1 = fmaxf(p1, cv * mv[1][q]);
                            p2 = fmaxf(p2, cv * mv[2][q]);
                        }
                    #pragma unroll
                    for (int off = 4; off <= 16; off <<= 1) {
                        p0 = fmaxf(p0, __shfl_xor_sync(0xffffffffu, p0, off));
                        p1 = fmaxf(p1, __shfl_xor_sync(0xffffffffu, p1, off));
                        p2 = fmaxf(p2, __shfl_xor_sync(0xffffffffu, p2, off));
                    }
                    if ((lane & 28) == 0) {
                        sR[((sm * 384 + 0 * 128 + o) << 2) + warp_m] = p0;
                        sR[((sm * 384 + 1 * 128 + o) << 2) + warp_m] = p1;
                        sR[((sm * 384 + 2 * 128 + o) << 2) + warp_m] = p2;
                    }
                }
            }
        }
        __syncthreads();

        for (int t = tid; t < 2 * 384; t += 512) {
            int sm = t / 384, tt = t % 384;
            const float* rp = &sR[t << 2];
            float R = fmaxf(fmaxf(rp[0], rp[1]), fmaxf(rp[2], rp[3]));
            out[(size_t)bs[sm] * OUTD + tt] = tanhf(R);
        }
    }
}

// ============================================================================
extern "C" void kernel_launch(void* const* d_in, const int* in_sizes, int n_in,
                              void* d_out, int out_size) {
    const int*   inp       = (const int*)d_in[0];
    const int*   pos1      = (const int*)d_in[1];
    const int*   pos2      = (const int*)d_in[2];
    const int*   loc       = (const int*)d_in[3];
    const int*   loc_mark  = (const int*)d_in[4];
    const int*   subtype   = (const int*)d_in[5];
    const int*   argRole   = (const int*)d_in[6];
    const float* maskL     = (const float*)d_in[7];
    const float* maskM     = (const float*)d_in[8];
    const float* maskR     = (const float*)d_in[9];
    const float* word_emb  = (const float*)d_in[10];
    const float* pos_emb   = (const float*)d_in[11];
    const float* event_emb = (const float*)d_in[12];
    const float* role_emb  = (const float*)d_in[13];
    const float* conv_w    = (const float*)d_in[14];
    const float* conv_b    = (const float*)d_in[15];
    float* out = (float*)d_out;

    int prep_elems = KT * 16 * 32 * 2 + 3 * CCONST * DC;
    prep_kernel<<<(prep_elems + 255) / 256, 256>>>(conv_w);
    const_kernel<<<SZ / GS, 256>>>(loc, loc_mark, subtype, argRole,
                                   word_emb, event_emb, role_emb, out);
    cudaFuncSetAttribute(main_kernel, cudaFuncAttributeMaxDynamicSharedMemorySize, SMB_TOT);
    main_kernel<<<148, 512, SMB_TOT>>>(inp, pos1, pos2, maskL, maskM, maskR,
                                       word_emb, pos_emb, conv_b, out);
}

// round 9
// speedup vs baseline: 4.7803x; 1.0089x over previous
#include <cuda_runtime.h>
#include <cuda_fp16.h>
#include <math.h>
#include <stdint.h>

#define SZ     4096
#define SEN    128
#define DC     128
#define OUTD   984
#define CCONST 160
#define GS     8
#define KT     21             // k16 steps = 3 taps * 7
#define VSTR2  136            // half2-word stride (136%32==8 -> conflict-free)
#define NQ     56             // 112 channels / 2 per half2
#define VH_BYTES (NQ * VSTR2 * 4)   // 30464 per sample tile

// SMEM byte offsets
#define SMB_B    0                      // 21*8*32 uint4 = 86016
#define SMB_VH   86016                  // 4 tiles * 30464 = 121856
#define SMB_MASK 207872                 // 2*384 f = 3072
#define SMB_C    210944                 // 2*128 f = 1024
#define SMB_B0   211968                 // 1024
#define SMB_B2   212992                 // 1024
#define SMB_R    214016                 // 2*384*4 f = 12288
#define SMB_TOT  226304

typedef unsigned long long u64;

__device__ __align__(16) uint32_t gBfh[KT * 8 * 32 * 4];   // fp16 B frags, uint4-grouped
__device__ __align__(16) float gW2[3 * CCONST * DC];
__device__ __align__(16) float gBase[SZ * 3 * DC];

__device__ __forceinline__ uint32_t smem_u32(const void* p) {
    uint32_t a;
    asm("{ .reg .u64 t; cvta.to.shared.u64 t, %1; cvt.u32.u64 %0, t; }" : "=r"(a) : "l"(p));
    return a;
}
#define CP16(dst_u32, src_ptr) \
    asm volatile("cp.async.cg.shared.global [%0], [%1], 16;" :: "r"(dst_u32), "l"(src_ptr) : "memory")
#define CP_COMMIT() asm volatile("cp.async.commit_group;" ::: "memory")
#define CP_WAIT0()  asm volatile("cp.async.wait_group 0;" ::: "memory")
#define MMA_F16(d, a0, a1, a2, a3, bx, by) \
    asm volatile("mma.sync.aligned.m16n8k16.row.col.f32.f16.f16.f32 " \
        "{%0,%1,%2,%3},{%4,%5,%6,%7},{%8,%9},{%0,%1,%2,%3};" \
        : "+f"(d[0]), "+f"(d[1]), "+f"(d[2]), "+f"(d[3]) \
        : "r"(a0), "r"(a1), "r"(a2), "r"(a3), "r"(bx), "r"(by))

// ============================================================================
// P0: fp16 B fragments grouped for LDS.128: [kt][np][lane][4], np = nt>>1,
// word w = (nt&1)*2 + r.  Frag halves at k=(lane&3)*2 + r*8 + {0,1},
// o = nt*8 + lane>>2 ; j = kt*16 + k -> tap=j/112, c=j%112 (0 for c>=110).
// ============================================================================
__global__ void prep_kernel(const float* __restrict__ conv_w) {
    int idx = blockIdx.x * blockDim.x + threadIdx.x;
    if (idx < KT * 16 * 32 * 2) {
        int r = idx & 1, lane = (idx >> 1) & 31, nt = (idx >> 6) & 15, kt = idx >> 10;
        int o = nt * 8 + (lane >> 2);
        int j0 = kt * 16 + (lane & 3) * 2 + r * 8;
        float v0 = 0.f, v1 = 0.f;
        { int tap = j0 / 112, c = j0 % 112; if (c < 110) v0 = conv_w[o * 810 + c * 3 + tap]; }
        { int j1 = j0 + 1; int tap = j1 / 112, c = j1 % 112; if (c < 110) v1 = conv_w[o * 810 + c * 3 + tap]; }
        __half2 h = __floats2half2_rn(v0, v1);
        gBfh[((kt * 8 + (nt >> 1)) * 32 + lane) * 4 + (nt & 1) * 2 + r] = *(uint32_t*)&h;
    } else {
        int i2 = idx - KT * 16 * 32 * 2;
        if (i2 < 3 * CCONST * DC) {
            int kc = i2 / DC, o = i2 % DC;
            int k = kc / CCONST, c2 = kc % CCONST;
            gW2[i2] = conv_w[o * 810 + (110 + c2) * 3 + k];
        }
    }
}

// ============================================================================
// P1: constant-channel base + loc branch (exact fp32, unchanged).
// ============================================================================
__global__ __launch_bounds__(256) void const_kernel(
    const int* __restrict__ loc, const int* __restrict__ loc_mark,
    const int* __restrict__ subtype, const int* __restrict__ argRole,
    const float* __restrict__ word_emb, const float* __restrict__ event_emb,
    const float* __restrict__ role_emb, float* __restrict__ out)
{
    __shared__ float evrl[GS][CCONST];
    int tid = threadIdx.x;
    int b0 = blockIdx.x * GS;
    for (int i = tid; i < GS * CCONST; i += 256) {
        int g = i / CCONST, c2 = i % CCONST;
        int b = b0 + g;
        float v;
        if (c2 < 32) v = event_emb[subtype[b] * 32 + c2];
        else { int r = (c2 - 32) >> 4, q = (c2 - 32) & 15; v = role_emb[argRole[b * 8 + r] * 16 + q]; }
        evrl[g][c2] = v;
    }
    __syncthreads();
    for (int t = tid; t < 3 * DC; t += 256) {
        int o = t % DC, k = t / DC;
        float s[GS];
        #pragma unroll
        for (int g = 0; g < GS; g++) s[g] = 0.f;
        const float* w2 = &gW2[k * CCONST * DC + o];
        for (int c2 = 0; c2 < CCONST; c2++) {
            float w = w2[c2 * DC];
            #pragma unroll
            for (int g = 0; g < GS; g++) s[g] = fmaf(evrl[g][c2], w, s[g]);
        }
        #pragma unroll
        for (int g = 0; g < GS; g++) gBase[(size_t)(b0 + g) * (3 * DC) + t] = s[g];
    }
    int g = tid >> 5, lane = tid & 31;
    int b = b0 + g;
    const int* lb = &loc[b * 16];
    int mark = loc_mark[b];
    float* ob = &out[(size_t)b * OUTD + 384];
    for (int d = lane; d < 100; d += 32) {
        #pragma unroll
        for (int i = 0; i < 4; i++) ob[i * 100 + d] = tanhf(word_emb[lb[i] * 100 + d]);
        float s = 0.f;
        for (int i = 0; i < mark; i++) s += word_emb[lb[4 + i] * 100 + d];
        ob[400 + d] = tanhf(s / (float)mark);
        ob[500 + d] = tanhf(word_emb[lb[4 + mark] * 100 + d]);
    }
}

// ============================================================================
// v-tile gather for one pair into buffer `buf` (no syncs inside).
// ============================================================================
__device__ __forceinline__ void gather_pair(
    char* smb, int pr, int buf, int tid,
    const int* __restrict__ inp, const int* __restrict__ pos1, const int* __restrict__ pos2,
    const float* __restrict__ word_emb, const float* __restrict__ pos_emb)
{
    #pragma unroll
    for (int sm = 0; sm < 2; sm++) {
        const int b = 2 * pr + sm;
        __half2* vh2 = (__half2*)(smb + SMB_VH + (buf * 2 + sm) * VH_BYTES);
        __half*  vh  = (__half*)(smb + SMB_VH + (buf * 2 + sm) * VH_BYTES);
        const int* inpb = inp + b * SEN;
        for (int idx = tid; idx < SEN * 25; idx += 512) {
            int s = idx / 25, q4 = idx % 25;
            float4 w4 = ((const float4*)word_emb)[(size_t)inpb[s] * 25 + q4];
            vh2[(2 * q4 + 0) * VSTR2 + s + 1] = __floats2half2_rn(w4.x, w4.y);
            vh2[(2 * q4 + 1) * VSTR2 + s + 1] = __floats2half2_rn(w4.z, w4.w);
        }
        const int* p1b = pos1 + b * SEN;
        const int* p2b = pos2 + b * SEN;
        for (int idx = tid; idx < SEN * 10; idx += 512) {
            int s = idx / 10, r = idx % 10;
            int row = (r < 5) ? p1b[s] : p2b[s];
            int c = 100 + r;
            vh[(c >> 1) * (2 * VSTR2) + (s + 1) * 2 + (c & 1)] =
                __float2half_rn(pos_emb[row * 5 + (r % 5)]);
        }
    }
}

// ============================================================================
// Main: 148 persistent CTAs (512 thr). B resident; 2 samples/iter; v-tiles
// double-buffered with the next pair's gather issued before the mainloop
// (latency hidden under MMA work). Warp grid 4(M) x 4(N).
// ============================================================================
__global__ __launch_bounds__(512, 1) void main_kernel(
    const int* __restrict__ inp, const int* __restrict__ pos1, const int* __restrict__ pos2,
    const float* __restrict__ maskL, const float* __restrict__ maskM, const float* __restrict__ maskR,
    const float* __restrict__ word_emb, const float* __restrict__ pos_emb,
    const float* __restrict__ conv_b, float* __restrict__ out)
{
    extern __shared__ char smb[];
    float* sMask = (float*)(smb + SMB_MASK);   // [sm][3*128]
    float* sC    = (float*)(smb + SMB_C);      // [sm][128]
    float* sB0   = (float*)(smb + SMB_B0);
    float* sB2   = (float*)(smb + SMB_B2);
    float* sR    = (float*)(smb + SMB_R);      // [sm][384][4]

    const int tid = threadIdx.x;
    const int lane = tid & 31, warp = tid >> 5;
    const int warp_m = warp & 3, warp_n = warp >> 2;

    // ---- one-time: load B (84KB), zero all 4 v tiles, gather first pair ----
    {
        uint32_t dst = smem_u32(smb + SMB_B);
        const uint32_t* src = gBfh;
        for (int i = tid; i < KT * 8 * 32 * 4 / 4; i += 512)
            CP16(dst + i * 16, src + i * 4);
        CP_COMMIT();
    }
    for (int i = tid; i < 4 * NQ * VSTR2; i += 512)
        ((uint32_t*)(smb + SMB_VH))[i] = 0u;
    CP_WAIT0();
    __syncthreads();
    if (blockIdx.x < SZ / 2)
        gather_pair(smb, blockIdx.x, 0, tid, inp, pos1, pos2, word_emb, pos_emb);
    __syncthreads();

    const int a_base = (lane & 3) * VSTR2 + warp_m * 32 + (lane >> 2);

    int it = 0;
    for (int p = blockIdx.x; p < SZ / 2; p += gridDim.x, ++it) {
        const int cur = it & 1;
        const int bs[2] = { 2 * p, 2 * p + 1 };

        // ---- stage masks + bias for current pair (unsynced; visible after
        //      the post-mainloop barrier) ----
        #pragma unroll
        for (int sm = 0; sm < 2; sm++) {
            const int b = bs[sm];
            for (int i = tid; i < 3 * SEN; i += 512) {
                sMask[sm * 384 + i] =
                      (i < 128) ? maskL[b * SEN + i]
                    : (i < 256) ? maskM[b * SEN + i - 128]
                                : maskR[b * SEN + i - 256];
            }
            if (tid < DC) {
                float b0v = gBase[(size_t)b * 384 + tid];
                float b1v = gBase[(size_t)b * 384 + 128 + tid];
                float b2v = gBase[(size_t)b * 384 + 256 + tid];
                sC[sm * 128 + tid] = conv_b[tid] + b0v + b1v + b2v;
                sB0[sm * 128 + tid] = b0v;
                sB2[sm * 128 + tid] = b2v;
            }
        }

        // ---- prefetch next pair's v tiles into the other buffer ----
        if (p + gridDim.x < SZ / 2)
            gather_pair(smb, p + gridDim.x, cur ^ 1, tid, inp, pos1, pos2, word_emb, pos_emb);

        // ---- GEMM mainloop on current buffers ----
        float acc[2][2][4][4];
        #pragma unroll
        for (int sm = 0; sm < 2; sm++)
            #pragma unroll
            for (int mt = 0; mt < 2; mt++)
                #pragma unroll
                for (int nt = 0; nt < 4; nt++)
                    #pragma unroll
                    for (int r = 0; r < 4; r++) acc[sm][mt][nt][r] = 0.f;

        const uint32_t* svu0 = (const uint32_t*)(smb + SMB_VH + (cur * 2 + 0) * VH_BYTES);
        const uint32_t* svu1 = (const uint32_t*)(smb + SMB_VH + (cur * 2 + 1) * VH_BYTES);
        const uint4* sB4 = (const uint4*)(smb + SMB_B);

        #pragma unroll
        for (int tap = 0; tap < 3; tap++) {
            #pragma unroll
            for (int ktl = 0; ktl < 7; ktl++) {
                const int kt = tap * 7 + ktl;
                const int ab = ktl * 8 * VSTR2 + tap + a_base;
                uint32_t am[2][2][4];
                #pragma unroll
                for (int mt = 0; mt < 2; mt++) {
                    int o16 = mt * 16;
                    am[0][mt][0] = svu0[ab + o16];
                    am[0][mt][1] = svu0[ab + o16 + 8];
                    am[0][mt][2] = svu0[ab + o16 + 4 * VSTR2];
                    am[0][mt][3] = svu0[ab + o16 + 4 * VSTR2 + 8];
                    am[1][mt][0] = svu1[ab + o16];
                    am[1][mt][1] = svu1[ab + o16 + 8];
                    am[1][mt][2] = svu1[ab + o16 + 4 * VSTR2];
                    am[1][mt][3] = svu1[ab + o16 + 4 * VSTR2 + 8];
                }
                const uint4* bw = sB4 + kt * 256 + (warp_n * 2) * 32;
                uint4 bb0 = bw[lane];
                uint4 bb1 = bw[32 + lane];
                #pragma unroll
                for (int sm = 0; sm < 2; sm++) {
                    #pragma unroll
                    for (int mt = 0; mt < 2; mt++) {
                        MMA_F16(acc[sm][mt][0], am[sm][mt][0], am[sm][mt][1], am[sm][mt][2], am[sm][mt][3], bb0.x, bb0.y);
                        MMA_F16(acc[sm][mt][1], am[sm][mt][0], am[sm][mt][1], am[sm][mt][2], am[sm][mt][3], bb0.z, bb0.w);
                        MMA_F16(acc[sm][mt][2], am[sm][mt][0], am[sm][mt][1], am[sm][mt][2], am[sm][mt][3], bb1.x, bb1.y);
                        MMA_F16(acc[sm][mt][3], am[sm][mt][0], am[sm][mt][1], am[sm][mt][2], am[sm][mt][3], bb1.z, bb1.w);
                    }
                }
            }
        }

        __syncthreads();   // masks/bias visible; next-pair gather long since done

        // ---- epilogue per sample ----
        #pragma unroll
        for (int sm = 0; sm < 2; sm++) {
            float mv[3][4];
            int srow[4];
            #pragma unroll
            for (int mt = 0; mt < 2; mt++)
                #pragma unroll
                for (int rg = 0; rg < 2; rg++) {
                    int s = warp_m * 32 + mt * 16 + (lane >> 2) + rg * 8;
                    int q = mt * 2 + rg;
                    srow[q] = s;
                    mv[0][q] = sMask[sm * 384 + s];
                    mv[1][q] = sMask[sm * 384 + 128 + s];
                    mv[2][q] = sMask[sm * 384 + 256 + s];
                }
            #pragma unroll
            for (int nt = 0; nt < 4; nt++) {
                #pragma unroll
                for (int h = 0; h < 2; h++) {
                    int o = warp_n * 32 + nt * 8 + 2 * (lane & 3) + h;
                    float C = sC[sm * 128 + o];
                    float B0v = sB0[sm * 128 + o], B2v = sB2[sm * 128 + o];
                    float p0 = -3.0e38f, p1 = -3.0e38f, p2 = -3.0e38f;
                    #pragma unroll
                    for (int mt = 0; mt < 2; mt++)
                        #pragma unroll
                        for (int rg = 0; rg < 2; rg++) {
                            int q = mt * 2 + rg;
                            int s = srow[q];
                            float cv = acc[sm][mt][nt][rg * 2 + h] + C;
                            if (s == 0)   cv -= B0v;
                            if (s == 127) cv -= B2v;
                            p0 = fmaxf(p0, cv * mv[0][q]);
                            p1 = fmaxf(p1, cv * mv[1][q]);
                            p2 = fmaxf(p2, cv * mv[2][q]);
                        }
                    #pragma unroll
                    for (int off = 4; off <= 16; off <<= 1) {
                        p0 = fmaxf(p0, __shfl_xor_sync(0xffffffffu, p0, off));
                        p1 = fmaxf(p1, __shfl_xor_sync(0xffffffffu, p1, off));
                        p2 = fmaxf(p2, __shfl_xor_sync(0xffffffffu, p2, off));
                    }
                    if ((lane & 28) == 0) {
                        sR[((sm * 384 + 0 * 128 + o) << 2) + warp_m] = p0;
                        sR[((sm * 384 + 1 * 128 + o) << 2) + warp_m] = p1;
                        sR[((sm * 384 + 2 * 128 + o) << 2) + warp_m] = p2;
                    }
                }
            }
        }
        __syncthreads();

        for (int t = tid; t < 2 * 384; t += 512) {
            int sm = t / 384, tt = t % 384;
            const float* rp = &sR[t << 2];
            float R = fmaxf(fmaxf(rp[0], rp[1]), fmaxf(rp[2], rp[3]));
            out[(size_t)bs[sm] * OUTD + tt] = tanhf(R);
        }
        __syncthreads();   // sR consumed; next-pair v tiles become current
    }
}

// ============================================================================
extern "C" void kernel_launch(void* const* d_in, const int* in_sizes, int n_in,
                              void* d_out, int out_size) {
    const int*   inp       = (const int*)d_in[0];
    const int*   pos1      = (const int*)d_in[1];
    const int*   pos2      = (const int*)d_in[2];
    const int*   loc       = (const int*)d_in[3];
    const int*   loc_mark  = (const int*)d_in[4];
    const int*   subtype   = (const int*)d_in[5];
    const int*   argRole   = (const int*)d_in[6];
    const float* maskL     = (const float*)d_in[7];
    const float* maskM     = (const float*)d_in[8];
    const float* maskR     = (const float*)d_in[9];
    const float* word_emb  = (const float*)d_in[10];
    const float* pos_emb   = (const float*)d_in[11];
    const float* event_emb = (const float*)d_in[12];
    const float* role_emb  = (const float*)d_in[13];
    const float* conv_w    = (const float*)d_in[14];
    const float* conv_b    = (const float*)d_in[15];
    float* out = (float*)d_out;

    int prep_elems = KT * 16 * 32 * 2 + 3 * CCONST * DC;
    prep_kernel<<<(prep_elems + 255) / 256, 256>>>(conv_w);
    const_kernel<<<SZ / GS, 256>>>(loc, loc_mark, subtype, argRole,
                                   word_emb, event_emb, role_emb, out);
    cudaFuncSetAttribute(main_kernel, cudaFuncAttributeMaxDynamicSharedMemorySize, SMB_TOT);
    main_kernel<<<148, 512, SMB_TOT>>>(inp, pos1, pos2, maskL, maskM, maskR,
                                       word_emb, pos_emb, conv_b, out);
}

// round 10
// speedup vs baseline: 4.9177x; 1.0287x over previous
#include <cuda_runtime.h>
#include <cuda_fp16.h>
#include <math.h>
#include <stdint.h>

#define SZ     4096
#define SEN    128
#define DC     128
#define OUTD   984
#define CCONST 160
#define GS     8
#define KT     21             // k16 steps = 3 taps * 7
#define VROWB  240            // bytes per v-tile row: 120 halves (112 data + 8 pad)
#define VH_BYTES (130 * VROWB)   // 31200 per sample tile (rows x = 0..129)

// SMEM byte offsets
#define SMB_B    0                      // 21*8*32 uint4 = 86016
#define SMB_VH   86016                  // 4 tiles * 31200 = 124800
#define SMB_MASK 210816                 // 2*384 f = 3072
#define SMB_C    213888                 // 2*128 f = 1024
#define SMB_B0   214912                 // 1024
#define SMB_B2   215936                 // 1024
#define SMB_R    216960                 // 2*384*4 f = 12288
#define SMB_TOT  229248

typedef unsigned long long u64;

__device__ __align__(16) uint32_t gBfh[KT * 8 * 32 * 4];   // fp16 B frags, uint4-grouped
__device__ __align__(16) float gW2[3 * CCONST * DC];
__device__ __align__(16) float gBase[SZ * 3 * DC];

__device__ __forceinline__ uint32_t smem_u32(const void* p) {
    uint32_t a;
    asm("{ .reg .u64 t; cvta.to.shared.u64 t, %1; cvt.u32.u64 %0, t; }" : "=r"(a) : "l"(p));
    return a;
}
#define CP16(dst_u32, src_ptr) \
    asm volatile("cp.async.cg.shared.global [%0], [%1], 16;" :: "r"(dst_u32), "l"(src_ptr) : "memory")
#define CP_COMMIT() asm volatile("cp.async.commit_group;" ::: "memory")
#define CP_WAIT0()  asm volatile("cp.async.wait_group 0;" ::: "memory")
#define LDSM4(r0, r1, r2, r3, addr) \
    asm volatile("ldmatrix.sync.aligned.m8n8.x4.shared.b16 {%0,%1,%2,%3}, [%4];" \
        : "=r"(r0), "=r"(r1), "=r"(r2), "=r"(r3) : "r"(addr))
#define MMA_F16(d, a0, a1, a2, a3, bx, by) \
    asm volatile("mma.sync.aligned.m16n8k16.row.col.f32.f16.f16.f32 " \
        "{%0,%1,%2,%3},{%4,%5,%6,%7},{%8,%9},{%0,%1,%2,%3};" \
        : "+f"(d[0]), "+f"(d[1]), "+f"(d[2]), "+f"(d[3]) \
        : "r"(a0), "r"(a1), "r"(a2), "r"(a3), "r"(bx), "r"(by))

// ============================================================================
// P0: fp16 B fragments grouped for LDS.128 (unchanged layout) + gW2.
// ============================================================================
__global__ void prep_kernel(const float* __restrict__ conv_w) {
    int idx = blockIdx.x * blockDim.x + threadIdx.x;
    if (idx < KT * 16 * 32 * 2) {
        int r = idx & 1, lane = (idx >> 1) & 31, nt = (idx >> 6) & 15, kt = idx >> 10;
        int o = nt * 8 + (lane >> 2);
        int j0 = kt * 16 + (lane & 3) * 2 + r * 8;
        float v0 = 0.f, v1 = 0.f;
        { int tap = j0 / 112, c = j0 % 112; if (c < 110) v0 = conv_w[o * 810 + c * 3 + tap]; }
        { int j1 = j0 + 1; int tap = j1 / 112, c = j1 % 112; if (c < 110) v1 = conv_w[o * 810 + c * 3 + tap]; }
        __half2 h = __floats2half2_rn(v0, v1);
        gBfh[((kt * 8 + (nt >> 1)) * 32 + lane) * 4 + (nt & 1) * 2 + r] = *(uint32_t*)&h;
    } else {
        int i2 = idx - KT * 16 * 32 * 2;
        if (i2 < 3 * CCONST * DC) {
            int kc = i2 / DC, o = i2 % DC;
            int k = kc / CCONST, c2 = kc % CCONST;
            gW2[i2] = conv_w[o * 810 + (110 + c2) * 3 + k];
        }
    }
}

// ============================================================================
// P1: constant-channel base + loc branch (exact fp32, unchanged).
// ============================================================================
__global__ __launch_bounds__(256) void const_kernel(
    const int* __restrict__ loc, const int* __restrict__ loc_mark,
    const int* __restrict__ subtype, const int* __restrict__ argRole,
    const float* __restrict__ word_emb, const float* __restrict__ event_emb,
    const float* __restrict__ role_emb, float* __restrict__ out)
{
    __shared__ float evrl[GS][CCONST];
    int tid = threadIdx.x;
    int b0 = blockIdx.x * GS;
    for (int i = tid; i < GS * CCONST; i += 256) {
        int g = i / CCONST, c2 = i % CCONST;
        int b = b0 + g;
        float v;
        if (c2 < 32) v = event_emb[subtype[b] * 32 + c2];
        else { int r = (c2 - 32) >> 4, q = (c2 - 32) & 15; v = role_emb[argRole[b * 8 + r] * 16 + q]; }
        evrl[g][c2] = v;
    }
    __syncthreads();
    for (int t = tid; t < 3 * DC; t += 256) {
        int o = t % DC, k = t / DC;
        float s[GS];
        #pragma unroll
        for (int g = 0; g < GS; g++) s[g] = 0.f;
        const float* w2 = &gW2[k * CCONST * DC + o];
        for (int c2 = 0; c2 < CCONST; c2++) {
            float w = w2[c2 * DC];
            #pragma unroll
            for (int g = 0; g < GS; g++) s[g] = fmaf(evrl[g][c2], w, s[g]);
        }
        #pragma unroll
        for (int g = 0; g < GS; g++) gBase[(size_t)(b0 + g) * (3 * DC) + t] = s[g];
    }
    int g = tid >> 5, lane = tid & 31;
    int b = b0 + g;
    const int* lb = &loc[b * 16];
    int mark = loc_mark[b];
    float* ob = &out[(size_t)b * OUTD + 384];
    for (int d = lane; d < 100; d += 32) {
        #pragma unroll
        for (int i = 0; i < 4; i++) ob[i * 100 + d] = tanhf(word_emb[lb[i] * 100 + d]);
        float s = 0.f;
        for (int i = 0; i < mark; i++) s += word_emb[lb[4 + i] * 100 + d];
        ob[400 + d] = tanhf(s / (float)mark);
        ob[500 + d] = tanhf(word_emb[lb[4 + mark] * 100 + d]);
    }
}

// ============================================================================
// v-tile gather (s-major rows): row x = s+1, halves [c]; 8B store per float4.
// ============================================================================
__device__ __forceinline__ void gather_pair(
    char* smb, int pr, int buf, int tid,
    const int* __restrict__ inp, const int* __restrict__ pos1, const int* __restrict__ pos2,
    const float* __restrict__ word_emb, const float* __restrict__ pos_emb)
{
    #pragma unroll
    for (int sm = 0; sm < 2; sm++) {
        const int b = 2 * pr + sm;
        char* base = smb + SMB_VH + (buf * 2 + sm) * VH_BYTES;
        const int* inpb = inp + b * SEN;
        for (int idx = tid; idx < SEN * 25; idx += 512) {
            int s = idx / 25, q4 = idx % 25;
            float4 w4 = ((const float4*)word_emb)[(size_t)inpb[s] * 25 + q4];
            __half2 h01 = __floats2half2_rn(w4.x, w4.y);
            __half2 h23 = __floats2half2_rn(w4.z, w4.w);
            uint2 val = make_uint2(*(uint32_t*)&h01, *(uint32_t*)&h23);
            *(uint2*)(base + (s + 1) * VROWB + q4 * 8) = val;
        }
        const int* p1b = pos1 + b * SEN;
        const int* p2b = pos2 + b * SEN;
        for (int idx = tid; idx < SEN * 10; idx += 512) {
            int s = idx / 10, r = idx % 10;
            int row = (r < 5) ? p1b[s] : p2b[s];
            *(__half*)(base + (s + 1) * VROWB + (100 + r) * 2) =
                __float2half_rn(pos_emb[row * 5 + (r % 5)]);
        }
    }
}

// ============================================================================
// Main: 148 persistent CTAs (512 thr). B resident; 2 samples/iter, double-
// buffered v-tiles with prefetch. A via ldmatrix.x4 (4 LDSM vs 16 LDS.32
// per warp per kstep). Warp grid 4(M) x 4(N).
// ============================================================================
__global__ __launch_bounds__(512, 1) void main_kernel(
    const int* __restrict__ inp, const int* __restrict__ pos1, const int* __restrict__ pos2,
    const float* __restrict__ maskL, const float* __restrict__ maskM, const float* __restrict__ maskR,
    const float* __restrict__ word_emb, const float* __restrict__ pos_emb,
    const float* __restrict__ conv_b, float* __restrict__ out)
{
    extern __shared__ char smb[];
    float* sMask = (float*)(smb + SMB_MASK);   // [sm][3*128]
    float* sC    = (float*)(smb + SMB_C);      // [sm][128]
    float* sB0   = (float*)(smb + SMB_B0);
    float* sB2   = (float*)(smb + SMB_B2);
    float* sR    = (float*)(smb + SMB_R);      // [sm][384][4]

    const int tid = threadIdx.x;
    const int lane = tid & 31, warp = tid >> 5;
    const int warp_m = warp & 3, warp_n = warp >> 2;
    const uint32_t smb_u = smem_u32(smb);

    // ---- one-time: load B (84KB), zero all 4 v tiles, gather first pair ----
    {
        uint32_t dst = smb_u + SMB_B;
        const uint32_t* src = gBfh;
        for (int i = tid; i < KT * 8 * 32 * 4 / 4; i += 512)
            CP16(dst + i * 16, src + i * 4);
        CP_COMMIT();
    }
    for (int i = tid; i < 4 * VH_BYTES / 4; i += 512)
        ((uint32_t*)(smb + SMB_VH))[i] = 0u;
    CP_WAIT0();
    __syncthreads();
    if (blockIdx.x < SZ / 2)
        gather_pair(smb, blockIdx.x, 0, tid, inp, pos1, pos2, word_emb, pos_emb);
    __syncthreads();

    // per-thread ldmatrix lane address part: row (lane&15), k-half block (lane>>4)*8
    const uint32_t rowsel = (uint32_t)((lane & 15) * VROWB + ((lane >> 4) << 4));

    int it = 0;
    for (int p = blockIdx.x; p < SZ / 2; p += gridDim.x, ++it) {
        const int cur = it & 1;
        const int bs[2] = { 2 * p, 2 * p + 1 };

        // ---- stage masks + bias (unsynced; visible after post-mainloop bar) ----
        #pragma unroll
        for (int sm = 0; sm < 2; sm++) {
            const int b = bs[sm];
            for (int i = tid; i < 3 * SEN; i += 512) {
                sMask[sm * 384 + i] =
                      (i < 128) ? maskL[b * SEN + i]
                    : (i < 256) ? maskM[b * SEN + i - 128]
                                : maskR[b * SEN + i - 256];
            }
            if (tid < DC) {
                float b0v = gBase[(size_t)b * 384 + tid];
                float b1v = gBase[(size_t)b * 384 + 128 + tid];
                float b2v = gBase[(size_t)b * 384 + 256 + tid];
                sC[sm * 128 + tid] = conv_b[tid] + b0v + b1v + b2v;
                sB0[sm * 128 + tid] = b0v;
                sB2[sm * 128 + tid] = b2v;
            }
        }

        // ---- prefetch next pair's v tiles ----
        if (p + gridDim.x < SZ / 2)
            gather_pair(smb, p + gridDim.x, cur ^ 1, tid, inp, pos1, pos2, word_emb, pos_emb);

        // ---- GEMM mainloop ----
        float acc[2][2][4][4];
        #pragma unroll
        for (int sm = 0; sm < 2; sm++)
            #pragma unroll
            for (int mt = 0; mt < 2; mt++)
                #pragma unroll
                for (int nt = 0; nt < 4; nt++)
                    #pragma unroll
                    for (int r = 0; r < 4; r++) acc[sm][mt][nt][r] = 0.f;

        const uint32_t vb0 = smb_u + SMB_VH + (cur * 2 + 0) * VH_BYTES + rowsel;
        const uint32_t vb1 = smb_u + SMB_VH + (cur * 2 + 1) * VH_BYTES + rowsel;
        const uint4* sB4 = (const uint4*)(smb + SMB_B);

        #pragma unroll
        for (int tap = 0; tap < 3; tap++) {
            #pragma unroll
            for (int ktl = 0; ktl < 7; ktl++) {
                const int kt = tap * 7 + ktl;
                const uint32_t roff = (uint32_t)((warp_m * 32 + tap) * VROWB + ktl * 32);
                uint32_t am[2][2][4];
                LDSM4(am[0][0][0], am[0][0][1], am[0][0][2], am[0][0][3], vb0 + roff);
                LDSM4(am[0][1][0], am[0][1][1], am[0][1][2], am[0][1][3], vb0 + roff + 16 * VROWB);
                LDSM4(am[1][0][0], am[1][0][1], am[1][0][2], am[1][0][3], vb1 + roff);
                LDSM4(am[1][1][0], am[1][1][1], am[1][1][2], am[1][1][3], vb1 + roff + 16 * VROWB);
                const uint4* bw = sB4 + kt * 256 + (warp_n * 2) * 32;
                uint4 bb0 = bw[lane];
                uint4 bb1 = bw[32 + lane];
                #pragma unroll
                for (int sm = 0; sm < 2; sm++) {
                    #pragma unroll
                    for (int mt = 0; mt < 2; mt++) {
                        MMA_F16(acc[sm][mt][0], am[sm][mt][0], am[sm][mt][1], am[sm][mt][2], am[sm][mt][3], bb0.x, bb0.y);
                        MMA_F16(acc[sm][mt][1], am[sm][mt][0], am[sm][mt][1], am[sm][mt][2], am[sm][mt][3], bb0.z, bb0.w);
                        MMA_F16(acc[sm][mt][2], am[sm][mt][0], am[sm][mt][1], am[sm][mt][2], am[sm][mt][3], bb1.x, bb1.y);
                        MMA_F16(acc[sm][mt][3], am[sm][mt][0], am[sm][mt][1], am[sm][mt][2], am[sm][mt][3], bb1.z, bb1.w);
                    }
                }
            }
        }

        __syncthreads();   // masks/bias visible; prefetch long since done

        // ---- epilogue per sample ----
        #pragma unroll
        for (int sm = 0; sm < 2; sm++) {
            float mv[3][4];
            int srow[4];
            #pragma unroll
            for (int mt = 0; mt < 2; mt++)
                #pragma unroll
                for (int rg = 0; rg < 2; rg++) {
                    int s = warp_m * 32 + mt * 16 + (lane >> 2) + rg * 8;
                    int q = mt * 2 + rg;
                    srow[q] = s;
                    mv[0][q] = sMask[sm * 384 + s];
                    mv[1][q] = sMask[sm * 384 + 128 + s];
                    mv[2][q] = sMask[sm * 384 + 256 + s];
                }
            #pragma unroll
            for (int nt = 0; nt < 4; nt++) {
                #pragma unroll
                for (int h = 0; h < 2; h++) {
                    int o = warp_n * 32 + nt * 8 + 2 * (lane & 3) + h;
                    float C = sC[sm * 128 + o];
                    float B0v = sB0[sm * 128 + o], B2v = sB2[sm * 128 + o];
                    float p0 = -3.0e38f, p1 = -3.0e38f, p2 = -3.0e38f;
                    #pragma unroll
                    for (int mt = 0; mt < 2; mt++)
                        #pragma unroll
                        for (int rg = 0; rg < 2; rg++) {
                            int q = mt * 2 + rg;
                            int s = srow[q];
                            float cv = acc[sm][mt][nt][rg * 2 + h] + C;
                            if (s == 0)   cv -= B0v;
                            if (s == 127) cv -= B2v;
                            p0 = fmaxf(p0, cv * mv[0][q]);
                            p1 = fmaxf(p1, cv * mv[1][q]);
                            p2 = fmaxf(p2, cv * mv[2][q]);
                        }
                    #pragma unroll
                    for (int off = 4; off <= 16; off <<= 1) {
                        p0 = fmaxf(p0, __shfl_xor_sync(0xffffffffu, p0, off));
                        p1 = fmaxf(p1, __shfl_xor_sync(0xffffffffu, p1, off));
                        p2 = fmaxf(p2, __shfl_xor_sync(0xffffffffu, p2, off));
                    }
                    if ((lane & 28) == 0) {
                        sR[((sm * 384 + 0 * 128 + o) << 2) + warp_m] = p0;
                        sR[((sm * 384 + 1 * 128 + o) << 2) + warp_m] = p1;
                        sR[((sm * 384 + 2 * 128 + o) << 2) + warp_m] = p2;
                    }
                }
            }
        }
        __syncthreads();

        for (int t = tid; t < 2 * 384; t += 512) {
            int sm = t / 384, tt = t % 384;
            const float* rp = &sR[t << 2];
            float R = fmaxf(fmaxf(rp[0], rp[1]), fmaxf(rp[2], rp[3]));
            out[(size_t)bs[sm] * OUTD + tt] = tanhf(R);
        }
        __syncthreads();   // sR consumed; buffers swap
    }
}

// ============================================================================
extern "C" void kernel_launch(void* const* d_in, const int* in_sizes, int n_in,
                              void* d_out, int out_size) {
    const int*   inp       = (const int*)d_in[0];
    const int*   pos1      = (const int*)d_in[1];
    const int*   pos2      = (const int*)d_in[2];
    const int*   loc       = (const int*)d_in[3];
    const int*   loc_mark  = (const int*)d_in[4];
    const int*   subtype   = (const int*)d_in[5];
    const int*   argRole   = (const int*)d_in[6];
    const float* maskL     = (const float*)d_in[7];
    const float* maskM     = (const float*)d_in[8];
    const float* maskR     = (const float*)d_in[9];
    const float* word_emb  = (const float*)d_in[10];
    const float* pos_emb   = (const float*)d_in[11];
    const float* event_emb = (const float*)d_in[12];
    const float* role_emb  = (const float*)d_in[13];
    const float* conv_w    = (const float*)d_in[14];
    const float* conv_b    = (const float*)d_in[15];
    float* out = (float*)d_out;

    int prep_elems = KT * 16 * 32 * 2 + 3 * CCONST * DC;
    prep_kernel<<<(prep_elems + 255) / 256, 256>>>(conv_w);
    const_kernel<<<SZ / GS, 256>>>(loc, loc_mark, subtype, argRole,
                                   word_emb, event_emb, role_emb, out);
    cudaFuncSetAttribute(main_kernel, cudaFuncAttributeMaxDynamicSharedMemorySize, SMB_TOT);
    main_kernel<<<148, 512, SMB_TOT>>>(inp, pos1, pos2, maskL, maskM, maskR,
                                       word_emb, pos_emb, conv_b, out);
}